// round 5
// baseline (speedup 1.0000x reference)
#include <cuda_runtime.h>
#include <cuda_bf16.h>
#include <mma.h>
#include <math.h>
#include <stdint.h>

using namespace nvcuda;

#define S_   1024
#define DM_  1024
#define B_   8
#define H_   16
#define D_   64

// ---------------- scratch (__device__ globals; no allocation) ----------------
__device__ __nv_bfloat16 g_Qhi[B_*H_*S_*D_];  // [b,h,s,d]
__device__ __nv_bfloat16 g_Qlo[B_*H_*S_*D_];
__device__ __nv_bfloat16 g_Khi[B_*H_*S_*D_];
__device__ __nv_bfloat16 g_Klo[B_*H_*S_*D_];
__device__ __nv_bfloat16 g_Vhi[B_*H_*S_*D_];
__device__ __nv_bfloat16 g_Vlo[B_*H_*S_*D_];
__device__ __nv_bfloat16 g_Ahi[B_*S_*DM_];    // activation hi/lo (inputs, then X)
__device__ __nv_bfloat16 g_Alo[B_*S_*DM_];
__device__ __nv_bfloat16 g_Whi[DM_*DM_];      // weight-transposed hi/lo [N][K]
__device__ __nv_bfloat16 g_Wlo[DM_*DM_];

// ---------------- helpers ----------------
__device__ __forceinline__ uint32_t smem_u32(const void* p) {
    uint32_t a;
    asm("{ .reg .u64 t; cvta.to.shared.u64 t, %1; cvt.u32.u64 %0, t; }"
        : "=r"(a) : "l"(p));
    return a;
}
__device__ __forceinline__ void cp16(uint32_t dst, const void* src) {
    asm volatile("cp.async.cg.shared.global [%0], [%1], 16;" :: "r"(dst), "l"(src));
}
__device__ __forceinline__ uint32_t pack2(float a, float b, float* ra, float* rb) {
    __nv_bfloat16 ha = __float2bfloat16(a), hb = __float2bfloat16(b);
    *ra = a - __bfloat162float(ha);
    *rb = b - __bfloat162float(hb);
    return (uint32_t)__bfloat16_as_ushort(ha) |
           ((uint32_t)__bfloat16_as_ushort(hb) << 16);
}
__device__ __forceinline__ uint32_t pack2lo(float a, float b) {
    __nv_bfloat16 ha = __float2bfloat16(a), hb = __float2bfloat16(b);
    return (uint32_t)__bfloat16_as_ushort(ha) |
           ((uint32_t)__bfloat16_as_ushort(hb) << 16);
}

// ---------------- conversion kernels ----------------
__global__ __launch_bounds__(256) void split_act(
    const float4* __restrict__ src, uint2* __restrict__ hi, uint2* __restrict__ lo, int n4)
{
    int i = blockIdx.x * 256 + threadIdx.x;
    if (i >= n4) return;
    float4 v = src[i];
    float rx, ry, rz, rw;
    uint2 h, l;
    h.x = pack2(v.x, v.y, &rx, &ry);
    h.y = pack2(v.z, v.w, &rz, &rw);
    l.x = pack2lo(rx, ry);
    l.y = pack2lo(rz, rw);
    hi[i] = h; lo[i] = l;
}

// weight transpose+split: out[n][k]; mode0 src=W[h][k][d] (n=h*64+d), mode1 src=Wo[k][n]
__global__ __launch_bounds__(256) void split_wT(
    const float* __restrict__ W, __nv_bfloat16* __restrict__ hi,
    __nv_bfloat16* __restrict__ lo, int mode)
{
    __shared__ float t[32][33];
    int k0 = blockIdx.x * 32, n0 = blockIdx.y * 32;
    int tx = threadIdx.x, ty = threadIdx.y;   // 32 x 8
    #pragma unroll
    for (int i = 0; i < 4; i++) {
        int k = k0 + ty + 8*i, n = n0 + tx;
        float v = mode ? W[(size_t)k * 1024 + n]
                       : W[(((size_t)(n >> 6)) * 1024 + k) * 64 + (n & 63)];
        t[ty + 8*i][tx] = v;
    }
    __syncthreads();
    #pragma unroll
    for (int i = 0; i < 4; i++) {
        int n = n0 + ty + 8*i, k = k0 + tx;
        float v = t[tx][ty + 8*i];
        __nv_bfloat16 h = __float2bfloat16(v);
        __nv_bfloat16 l = __float2bfloat16(v - __bfloat162float(h));
        hi[(size_t)n * 1024 + k] = h;
        lo[(size_t)n * 1024 + k] = l;
    }
}

// ---------------- wmma GEMM (bf16x3 emulated fp32) ----------------
#define LDSM   40
#define MATB   (128 * LDSM * 2)
#define STAGEB (4 * MATB)
#define GSMEM  (2 * STAGEB + 16 * 128 * 4)
#define EPLD   132

typedef wmma::fragment<wmma::matrix_a, 16,16,16, __nv_bfloat16, wmma::row_major> FragA;
typedef wmma::fragment<wmma::matrix_b, 16,16,16, __nv_bfloat16, wmma::col_major> FragBc;
typedef wmma::fragment<wmma::matrix_b, 16,16,16, __nv_bfloat16, wmma::row_major> FragBr;
typedef wmma::fragment<wmma::accumulator, 16,16,16, float> FragC;

__device__ __forceinline__ void issue_stage(
    const __nv_bfloat16* __restrict__ Ahi, const __nv_bfloat16* __restrict__ Alo,
    const __nv_bfloat16* __restrict__ Bhi, const __nv_bfloat16* __restrict__ Blo,
    uint32_t sbase, int stage, int m0, int n0, int k0, int tid)
{
    #pragma unroll
    for (int u = 0; u < 8; u++) {
        int chunk = u * 256 + tid;
        int mat = chunk >> 9;
        int r   = (chunk >> 2) & 127;
        int c   = chunk & 3;
        const __nv_bfloat16* g;
        if      (mat == 0) g = Ahi + (size_t)(m0 + r) * 1024 + k0 + c * 8;
        else if (mat == 1) g = Alo + (size_t)(m0 + r) * 1024 + k0 + c * 8;
        else if (mat == 2) g = Bhi + (size_t)(n0 + r) * 1024 + k0 + c * 8;
        else               g = Blo + (size_t)(n0 + r) * 1024 + k0 + c * 8;
        uint32_t dst = sbase + (uint32_t)(stage * STAGEB + mat * MATB + r * (LDSM*2) + c * 16);
        cp16(dst, g);
    }
    asm volatile("cp.async.commit_group;" ::: "memory");
}

__global__ __launch_bounds__(256) void mma_gemm(
    const __nv_bfloat16* __restrict__ Ahi, const __nv_bfloat16* __restrict__ Alo,
    const __nv_bfloat16* __restrict__ Bhi, const __nv_bfloat16* __restrict__ Blo,
    const float* __restrict__ bias, float* __restrict__ outF,
    __nv_bfloat16* __restrict__ outHi, __nv_bfloat16* __restrict__ outLo, int mode)
{
    extern __shared__ char sm[];
    float* sBias = (float*)(sm + 2 * STAGEB);
    const uint32_t sbase = smem_u32(sm);
    const int tid = threadIdx.x;
    const int wid = tid >> 5;
    const int m0 = blockIdx.y * 128;
    const int n0 = blockIdx.x * 128;
    const int wm = wid >> 2;
    const int wn = wid & 3;

    for (int idx = tid; idx < 16 * 128; idx += 256)
        sBias[idx] = bias[n0 + (idx & 127)];
    __syncthreads();

    FragC acc[4][2];
    #pragma unroll
    for (int i = 0; i < 4; i++)
        #pragma unroll
        for (int j = 0; j < 2; j++)
            wmma::load_matrix_sync(acc[i][j], sBias + wn*32 + j*16, 128, wmma::mem_row_major);

    issue_stage(Ahi, Alo, Bhi, Blo, sbase, 0, m0, n0, 0, tid);

    for (int kc = 0; kc < 32; kc++) {
        const int s = kc & 1;
        if (kc + 1 < 32) {
            issue_stage(Ahi, Alo, Bhi, Blo, sbase, s ^ 1, m0, n0, (kc + 1) * 32, tid);
            asm volatile("cp.async.wait_group 1;" ::: "memory");
        } else {
            asm volatile("cp.async.wait_group 0;" ::: "memory");
        }
        __syncthreads();

        const __nv_bfloat16* stg = (const __nv_bfloat16*)(sm + s * STAGEB);
        const __nv_bfloat16* sAh = stg;
        const __nv_bfloat16* sAl = stg + 128 * LDSM;
        const __nv_bfloat16* sBh = stg + 2 * 128 * LDSM;
        const __nv_bfloat16* sBl = stg + 3 * 128 * LDSM;

        #pragma unroll
        for (int ks = 0; ks < 2; ks++) {
            FragA ah[4], al[4];
            FragBc bh[2], bl[2];
            #pragma unroll
            for (int i = 0; i < 4; i++) {
                wmma::load_matrix_sync(ah[i], sAh + (wm*64 + i*16) * LDSM + ks*16, LDSM);
                wmma::load_matrix_sync(al[i], sAl + (wm*64 + i*16) * LDSM + ks*16, LDSM);
            }
            #pragma unroll
            for (int j = 0; j < 2; j++) {
                wmma::load_matrix_sync(bh[j], sBh + (wn*32 + j*16) * LDSM + ks*16, LDSM);
                wmma::load_matrix_sync(bl[j], sBl + (wn*32 + j*16) * LDSM + ks*16, LDSM);
            }
            #pragma unroll
            for (int i = 0; i < 4; i++)
                #pragma unroll
                for (int j = 0; j < 2; j++) {
                    wmma::mma_sync(acc[i][j], ah[i], bh[j], acc[i][j]);
                    wmma::mma_sync(acc[i][j], ah[i], bl[j], acc[i][j]);
                    wmma::mma_sync(acc[i][j], al[i], bh[j], acc[i][j]);
                }
        }
        __syncthreads();
    }

    if (mode == 1) {
        #pragma unroll
        for (int i = 0; i < 4; i++) {
            const int m = m0 + wm*64 + i*16;
            #pragma unroll
            for (int j = 0; j < 2; j++) {
                const int n = n0 + wn*32 + j*16;
                wmma::store_matrix_sync(outF + (size_t)m * 1024 + n, acc[i][j],
                                        1024, wmma::mem_row_major);
            }
        }
        return;
    }

    // mode 0: smem roundtrip, split to bf16 hi/lo at [b,h,s,d]
    float* sEpi = (float*)sm;
    #pragma unroll
    for (int i = 0; i < 4; i++)
        #pragma unroll
        for (int j = 0; j < 2; j++)
            wmma::store_matrix_sync(sEpi + (wm*64 + i*16) * EPLD + wn*32 + j*16,
                                    acc[i][j], EPLD, wmma::mem_row_major);
    __syncthreads();

    #pragma unroll
    for (int u = 0; u < 32; u++) {
        int e2 = u * 256 + tid;
        int r = e2 >> 6;
        int c = (e2 & 63) * 2;
        float v0 = sEpi[r * EPLD + c];
        float v1 = sEpi[r * EPLD + c + 1];
        float r0, r1;
        uint32_t hv = pack2(v0, v1, &r0, &r1);
        uint32_t lv = pack2lo(r0, r1);
        const int m = m0 + r, n = n0 + c;
        const int b = m >> 10, srow = m & 1023;
        const int h = n >> 6,  d = n & 63;
        size_t addr = ((((size_t)(b*16 + h)) * 1024 + srow) * 64 + d);
        *(uint32_t*)(outHi + addr) = hv;
        *(uint32_t*)(outLo + addr) = lv;
    }
}

// ---------------- tensor-core flash attention v2 ----------------------------
// CTA: 2 adjacent q-tiles (qt = 2*bx + group), 8 warps (4 per group),
// shared double-buffered K/V via cp.async, per-warp-local softmax rows.
#define ALD 72        // bf16 tile row stride (elements); 144 bytes
#define SLD 68        // fp32 tile row stride (elements); 272 bytes
#define TQB 9216      // one 64x64 bf16 tile with ALD pad (bytes)
#define oQ   0                      // 4 tiles: [g][hi/lo]       36864
#define oKV  36864                  // 2 stages x 4 tiles        73728
#define oP   110592                 // 2 groups x {hi,lo}        36864
#define oS   147456                 // 2 groups fp32 64xSLD      34816
#define oO   182272                 // 2 groups fp32 64xSLD      34816
#define oAux 217088                 // rm[128], rl[128]          1024
#define ATTN_SMEM 218112

__global__ __launch_bounds__(256) void attn_mma(
    const int* __restrict__ pad,
    __nv_bfloat16* __restrict__ Xhi, __nv_bfloat16* __restrict__ Xlo)
{
    extern __shared__ char sm[];
    const uint32_t sbase = smem_u32(sm);
    const int tid  = threadIdx.x;
    const int w    = tid >> 5, lane = tid & 31;
    const int g    = w >> 2,   wr   = w & 3;
    const int bx   = blockIdx.x;
    const int bh   = blockIdx.y;
    const int b    = bh >> 4, h = bh & 15;
    const int padb = pad[b];
    const int tlim = S_ - padb;
    const int qt   = bx * 2 + g;
    const int q0   = qt * 64;
    const size_t hoff = (size_t)bh * S_ * D_;

    float* rm = (float*)(sm + oAux);
    float* rl = rm + 128;
    float* sSg = (float*)(sm + oS + g * 17408);
    float* sOg = (float*)(sm + oO + g * 17408);
    const __nv_bfloat16* sPhg = (const __nv_bfloat16*)(sm + oP + g * 18432);
    const __nv_bfloat16* sPlg = (const __nv_bfloat16*)(sm + oP + g * 18432 + TQB);

    // init O, rm, rl
    for (int i = tid; i < 2 * 64 * SLD; i += 256) ((float*)(sm + oO))[i] = 0.f;
    if (tid < 128) { rm[tid] = -INFINITY; rl[tid] = 0.f; }

    // preload: Q tiles (both groups, hi+lo) + K/V tile 0 into stage 0; ONE group
    #pragma unroll
    for (int u = 0; u < 8; u++) {
        int c = u * 256 + tid;            // 2048 chunks
        int gm = c >> 9;                  // 0..3 : [g][hi/lo]
        int rc = c & 511;
        int r = rc >> 3, cc = rc & 7;
        const __nv_bfloat16* src = ((gm & 1) ? g_Qlo : g_Qhi)
            + hoff + (size_t)((bx*2 + (gm >> 1)) * 64 + r) * 64 + cc * 8;
        cp16(sbase + oQ + (uint32_t)(gm * TQB + r * 144 + cc * 16), src);
    }
    #pragma unroll
    for (int u = 0; u < 8; u++) {
        int c = u * 256 + tid;
        int mat = c >> 9;                 // Khi,Klo,Vhi,Vlo
        int rc = c & 511;
        int r = rc >> 3, cc = rc & 7;
        const __nv_bfloat16* src =
            (mat == 0 ? g_Khi : mat == 1 ? g_Klo : mat == 2 ? g_Vhi : g_Vlo)
            + hoff + (size_t)r * 64 + cc * 8;
        cp16(sbase + oKV + (uint32_t)(mat * TQB + r * 144 + cc * 16), src);
    }
    asm volatile("cp.async.commit_group;" ::: "memory");

    const int jtLast = (padb == 0) ? 15 : min(bx * 2 + 1, (tlim - 1) >> 6);

    FragA qh[4], ql[4];
    const int lr = lane >> 1, half = lane & 1;
    const int gi = g * 64 + wr * 16 + lr;
    const int srow = q0 + wr * 16 + lr;

    for (int jt = 0; jt <= jtLast; jt++) {
        const int s = jt & 1;
        const int t0 = jt * 64;
        if (jt < jtLast) {
            const int tn = (jt + 1) * 64;
            #pragma unroll
            for (int u = 0; u < 8; u++) {
                int c = u * 256 + tid;
                int mat = c >> 9;
                int rc = c & 511;
                int r = rc >> 3, cc = rc & 7;
                const __nv_bfloat16* src =
                    (mat == 0 ? g_Khi : mat == 1 ? g_Klo : mat == 2 ? g_Vhi : g_Vlo)
                    + hoff + (size_t)(tn + r) * 64 + cc * 8;
                cp16(sbase + oKV + (uint32_t)((s ^ 1) * 36864 + mat * TQB + r * 144 + cc * 16), src);
            }
            asm volatile("cp.async.commit_group;" ::: "memory");
            asm volatile("cp.async.wait_group 1;" ::: "memory");
        } else {
            asm volatile("cp.async.wait_group 0;" ::: "memory");
        }
        __syncthreads();

        const bool act = (padb == 0) || (jt <= qt && t0 < tlim);
        if (act) {
            const __nv_bfloat16* sKh = (const __nv_bfloat16*)(sm + oKV + s * 36864);
            const __nv_bfloat16* sKl = sKh + 64 * ALD;          // +TQB
            const __nv_bfloat16* sVh = sKh + 2 * 64 * ALD;
            const __nv_bfloat16* sVl = sKh + 3 * 64 * ALD;

            if (jt == 0) {
                const __nv_bfloat16* sQh = (const __nv_bfloat16*)(sm + oQ + g * 2 * TQB);
                const __nv_bfloat16* sQl = sQh + 64 * ALD;
                #pragma unroll
                for (int ks = 0; ks < 4; ks++) {
                    wmma::load_matrix_sync(qh[ks], sQh + (wr*16) * ALD + ks*16, ALD);
                    wmma::load_matrix_sync(ql[ks], sQl + (wr*16) * ALD + ks*16, ALD);
                }
            }

            // ---- S = Q K^T (bf16x3) ----
            {
                FragC acc[4];
                #pragma unroll
                for (int j = 0; j < 4; j++) wmma::fill_fragment(acc[j], 0.f);
                #pragma unroll
                for (int j = 0; j < 4; j++) {
                    #pragma unroll
                    for (int ks = 0; ks < 4; ks++) {
                        FragBc kh, kl;
                        wmma::load_matrix_sync(kh, sKh + (j*16) * ALD + ks*16, ALD);
                        wmma::load_matrix_sync(kl, sKl + (j*16) * ALD + ks*16, ALD);
                        wmma::mma_sync(acc[j], qh[ks], kh, acc[j]);
                        wmma::mma_sync(acc[j], qh[ks], kl, acc[j]);
                        wmma::mma_sync(acc[j], ql[ks], kh, acc[j]);
                    }
                }
                #pragma unroll
                for (int j = 0; j < 4; j++)
                    wmma::store_matrix_sync(sSg + (wr*16) * SLD + j*16, acc[j],
                                            SLD, wmma::mem_row_major);
            }
            __syncwarp();

            // ---- softmax (warp-local rows; 2 lanes per row) ----
            float alpha;
            {
                const float* Srow = sSg + (wr*16 + lr) * SLD + half * 32;
                const int tbase = t0 + half * 32;
                float mloc = -INFINITY;
                #pragma unroll
                for (int c = 0; c < 32; c++) {
                    const int t = tbase + c;
                    float v = Srow[c] * 0.03125f;
                    if ((t > srow) | (t >= tlim) | (padb == 0)) v -= 1e9f;
                    mloc = fmaxf(mloc, v);
                }
                mloc = fmaxf(mloc, __shfl_xor_sync(0xffffffffu, mloc, 1));
                const float mold = rm[gi];
                const float lold = rl[gi];
                __syncwarp();
                const float mnew = fmaxf(mold, mloc);
                alpha = __expf(mold - mnew);
                __nv_bfloat16* Pr = (__nv_bfloat16*)sPhg + (wr*16 + lr) * ALD + half * 32;
                __nv_bfloat16* Pl = (__nv_bfloat16*)sPlg + (wr*16 + lr) * ALD + half * 32;
                float lsum = 0.f;
                #pragma unroll
                for (int c = 0; c < 32; c++) {
                    const int t = tbase + c;
                    float v = Srow[c] * 0.03125f;
                    if ((t > srow) | (t >= tlim) | (padb == 0)) v -= 1e9f;
                    float p = __expf(v - mnew);
                    lsum += p;
                    __nv_bfloat16 ph = __float2bfloat16(p);
                    Pr[c] = ph;
                    Pl[c] = __float2bfloat16(p - __bfloat162float(ph));
                }
                lsum += __shfl_xor_sync(0xffffffffu, lsum, 1);
                if (half == 0) { rm[gi] = mnew; rl[gi] = lold * alpha + lsum; }
            }
            __syncwarp();

            // ---- PV (bf16x3), result overwrites S rows (warp-local) ----
            {
                FragA pfh[4], pfl[4];
                #pragma unroll
                for (int ks = 0; ks < 4; ks++) {
                    wmma::load_matrix_sync(pfh[ks], sPhg + (wr*16) * ALD + ks*16, ALD);
                    wmma::load_matrix_sync(pfl[ks], sPlg + (wr*16) * ALD + ks*16, ALD);
                }
                FragC oa[4];
                #pragma unroll
                for (int n = 0; n < 4; n++) wmma::fill_fragment(oa[n], 0.f);
                #pragma unroll
                for (int n = 0; n < 4; n++) {
                    #pragma unroll
                    for (int ks = 0; ks < 4; ks++) {
                        FragBr vh, vl;
                        wmma::load_matrix_sync(vh, sVh + (ks*16) * ALD + n*16, ALD);
                        wmma::load_matrix_sync(vl, sVl + (ks*16) * ALD + n*16, ALD);
                        wmma::mma_sync(oa[n], pfh[ks], vh, oa[n]);
                        wmma::mma_sync(oa[n], pfh[ks], vl, oa[n]);
                        wmma::mma_sync(oa[n], pfl[ks], vh, oa[n]);
                    }
                }
                #pragma unroll
                for (int n = 0; n < 4; n++)
                    wmma::store_matrix_sync(sSg + (wr*16) * SLD + n*16, oa[n],
                                            SLD, wmma::mem_row_major);
            }
            __syncwarp();

            // ---- O = O*alpha + PV ----
            {
                float* Orow = sOg + (wr*16 + lr) * SLD + half * 32;
                const float* Pv = sSg + (wr*16 + lr) * SLD + half * 32;
                #pragma unroll
                for (int c = 0; c < 32; c++)
                    Orow[c] = Orow[c] * alpha + Pv[c];
            }
            __syncwarp();
        }
        __syncthreads();
    }

    // epilogue: normalize, split, store (warp-local rows)
    {
        const float inv = 1.f / rl[gi];
        const float* Orow = sOg + (wr*16 + lr) * SLD + half * 32;
        const size_t base = ((size_t)(b * S_ + srow)) * DM_ + h * 64 + half * 32;
        #pragma unroll
        for (int c = 0; c < 32; c += 2) {
            float v0 = Orow[c] * inv, v1 = Orow[c+1] * inv;
            float r0, r1;
            uint32_t hv = pack2(v0, v1, &r0, &r1);
            uint32_t lv = pack2lo(r0, r1);
            *(uint32_t*)(Xhi + base + c) = hv;
            *(uint32_t*)(Xlo + base + c) = lv;
        }
    }
}

// ---------------------------------------------------------------------------
extern "C" void kernel_launch(void* const* d_in, const int* in_sizes, int n_in,
                              void* d_out, int out_size)
{
    const float* Q   = (const float*)d_in[0];
    const float* K   = (const float*)d_in[1];
    const float* V   = (const float*)d_in[2];
    const int*   pad = (const int*)  d_in[3];
    const float* Wq  = (const float*)d_in[4];
    const float* bq  = (const float*)d_in[5];
    const float* Wk  = (const float*)d_in[6];
    const float* bk  = (const float*)d_in[7];
    const float* Wv  = (const float*)d_in[8];
    const float* bv  = (const float*)d_in[9];
    const float* Wo  = (const float*)d_in[10];
    const float* bo  = (const float*)d_in[11];
    float* out = (float*)d_out;

    __nv_bfloat16 *qhi, *qlo, *khi, *klo, *vhi, *vlo, *ahi, *alo, *whi, *wlo;
    cudaGetSymbolAddress((void**)&qhi, g_Qhi);
    cudaGetSymbolAddress((void**)&qlo, g_Qlo);
    cudaGetSymbolAddress((void**)&khi, g_Khi);
    cudaGetSymbolAddress((void**)&klo, g_Klo);
    cudaGetSymbolAddress((void**)&vhi, g_Vhi);
    cudaGetSymbolAddress((void**)&vlo, g_Vlo);
    cudaGetSymbolAddress((void**)&ahi, g_Ahi);
    cudaGetSymbolAddress((void**)&alo, g_Alo);
    cudaGetSymbolAddress((void**)&whi, g_Whi);
    cudaGetSymbolAddress((void**)&wlo, g_Wlo);

    cudaFuncSetAttribute(mma_gemm,
                         cudaFuncAttributeMaxDynamicSharedMemorySize, GSMEM);
    cudaFuncSetAttribute(attn_mma,
                         cudaFuncAttributeMaxDynamicSharedMemorySize, ATTN_SMEM);

    const int n4 = (B_*S_*DM_) / 4;
    const dim3 gw(32, 32), bw(32, 8);
    const dim3 gg(8, 64);

    // Q projection
    split_wT<<<gw, bw>>>(Wq, whi, wlo, 0);
    split_act<<<n4/256, 256>>>((const float4*)Q, (uint2*)ahi, (uint2*)alo, n4);
    mma_gemm<<<gg, 256, GSMEM>>>(ahi, alo, whi, wlo, bq, nullptr, qhi, qlo, 0);
    // K projection
    split_wT<<<gw, bw>>>(Wk, whi, wlo, 0);
    split_act<<<n4/256, 256>>>((const float4*)K, (uint2*)ahi, (uint2*)alo, n4);
    mma_gemm<<<gg, 256, GSMEM>>>(ahi, alo, whi, wlo, bk, nullptr, khi, klo, 0);
    // V projection
    split_wT<<<gw, bw>>>(Wv, whi, wlo, 0);
    split_act<<<n4/256, 256>>>((const float4*)V, (uint2*)ahi, (uint2*)alo, n4);
    mma_gemm<<<gg, 256, GSMEM>>>(ahi, alo, whi, wlo, bv, nullptr, vhi, vlo, 0);

    // attention -> X hi/lo into ahi/alo
    attn_mma<<<dim3(8, 128), 256, ATTN_SMEM>>>(pad, ahi, alo);

    // output projection (fp32 out)
    split_wT<<<gw, bw>>>(Wo, whi, wlo, 1);
    mma_gemm<<<gg, 256, GSMEM>>>(ahi, alo, whi, wlo, bo, out, nullptr, nullptr, 1);
}

// round 6
// speedup vs baseline: 1.1102x; 1.1102x over previous
#include <cuda_runtime.h>
#include <cuda_bf16.h>
#include <mma.h>
#include <math.h>
#include <stdint.h>

using namespace nvcuda;

#define S_   1024
#define DM_  1024
#define B_   8
#define H_   16
#define D_   64

// ---------------- scratch (__device__ globals; no allocation) ----------------
__device__ __nv_bfloat16 g_Qhi[B_*H_*S_*D_];  // [b,h,s,d]
__device__ __nv_bfloat16 g_Qlo[B_*H_*S_*D_];
__device__ __nv_bfloat16 g_Khi[B_*H_*S_*D_];
__device__ __nv_bfloat16 g_Klo[B_*H_*S_*D_];
__device__ __nv_bfloat16 g_Vhi[B_*H_*S_*D_];
__device__ __nv_bfloat16 g_Vlo[B_*H_*S_*D_];
__device__ __nv_bfloat16 g_Ahi[B_*S_*DM_];    // activation hi/lo (inputs, then X)
__device__ __nv_bfloat16 g_Alo[B_*S_*DM_];
__device__ __nv_bfloat16 g_Whi[DM_*DM_];      // weight-transposed hi/lo [N][K]
__device__ __nv_bfloat16 g_Wlo[DM_*DM_];

// ---------------- helpers ----------------
__device__ __forceinline__ uint32_t smem_u32(const void* p) {
    uint32_t a;
    asm("{ .reg .u64 t; cvta.to.shared.u64 t, %1; cvt.u32.u64 %0, t; }"
        : "=r"(a) : "l"(p));
    return a;
}
__device__ __forceinline__ void cp16(uint32_t dst, const void* src) {
    asm volatile("cp.async.cg.shared.global [%0], [%1], 16;" :: "r"(dst), "l"(src));
}
__device__ __forceinline__ uint32_t pack2(float a, float b, float* ra, float* rb) {
    __nv_bfloat16 ha = __float2bfloat16(a), hb = __float2bfloat16(b);
    *ra = a - __bfloat162float(ha);
    *rb = b - __bfloat162float(hb);
    return (uint32_t)__bfloat16_as_ushort(ha) |
           ((uint32_t)__bfloat16_as_ushort(hb) << 16);
}
__device__ __forceinline__ uint32_t pack2lo(float a, float b) {
    __nv_bfloat16 ha = __float2bfloat16(a), hb = __float2bfloat16(b);
    return (uint32_t)__bfloat16_as_ushort(ha) |
           ((uint32_t)__bfloat16_as_ushort(hb) << 16);
}

// ---------------- conversion kernels ----------------
__global__ __launch_bounds__(256) void split_act(
    const float4* __restrict__ src, uint2* __restrict__ hi, uint2* __restrict__ lo, int n4)
{
    int i = blockIdx.x * 256 + threadIdx.x;
    if (i >= n4) return;
    float4 v = src[i];
    float rx, ry, rz, rw;
    uint2 h, l;
    h.x = pack2(v.x, v.y, &rx, &ry);
    h.y = pack2(v.z, v.w, &rz, &rw);
    l.x = pack2lo(rx, ry);
    l.y = pack2lo(rz, rw);
    hi[i] = h; lo[i] = l;
}

// weight transpose+split: out[n][k]; mode0 src=W[h][k][d] (n=h*64+d), mode1 src=Wo[k][n]
__global__ __launch_bounds__(256) void split_wT(
    const float* __restrict__ W, __nv_bfloat16* __restrict__ hi,
    __nv_bfloat16* __restrict__ lo, int mode)
{
    __shared__ float t[32][33];
    int k0 = blockIdx.x * 32, n0 = blockIdx.y * 32;
    int tx = threadIdx.x, ty = threadIdx.y;   // 32 x 8
    #pragma unroll
    for (int i = 0; i < 4; i++) {
        int k = k0 + ty + 8*i, n = n0 + tx;
        float v = mode ? W[(size_t)k * 1024 + n]
                       : W[(((size_t)(n >> 6)) * 1024 + k) * 64 + (n & 63)];
        t[ty + 8*i][tx] = v;
    }
    __syncthreads();
    #pragma unroll
    for (int i = 0; i < 4; i++) {
        int n = n0 + ty + 8*i, k = k0 + tx;
        float v = t[tx][ty + 8*i];
        __nv_bfloat16 h = __float2bfloat16(v);
        __nv_bfloat16 l = __float2bfloat16(v - __bfloat162float(h));
        hi[(size_t)n * 1024 + k] = h;
        lo[(size_t)n * 1024 + k] = l;
    }
}

// ---------------- wmma GEMM (bf16x3 emulated fp32) ----------------
#define LDSM   40
#define MATB   (128 * LDSM * 2)
#define STAGEB (4 * MATB)
#define GSMEM  (2 * STAGEB + 16 * 128 * 4)
#define EPLD   132

typedef wmma::fragment<wmma::matrix_a, 16,16,16, __nv_bfloat16, wmma::row_major> FragA;
typedef wmma::fragment<wmma::matrix_b, 16,16,16, __nv_bfloat16, wmma::col_major> FragBc;
typedef wmma::fragment<wmma::matrix_b, 16,16,16, __nv_bfloat16, wmma::row_major> FragBr;
typedef wmma::fragment<wmma::accumulator, 16,16,16, float> FragC;

__device__ __forceinline__ void issue_stage(
    const __nv_bfloat16* __restrict__ Ahi, const __nv_bfloat16* __restrict__ Alo,
    const __nv_bfloat16* __restrict__ Bhi, const __nv_bfloat16* __restrict__ Blo,
    uint32_t sbase, int stage, int m0, int n0, int k0, int tid)
{
    #pragma unroll
    for (int u = 0; u < 8; u++) {
        int chunk = u * 256 + tid;
        int mat = chunk >> 9;
        int r   = (chunk >> 2) & 127;
        int c   = chunk & 3;
        const __nv_bfloat16* g;
        if      (mat == 0) g = Ahi + (size_t)(m0 + r) * 1024 + k0 + c * 8;
        else if (mat == 1) g = Alo + (size_t)(m0 + r) * 1024 + k0 + c * 8;
        else if (mat == 2) g = Bhi + (size_t)(n0 + r) * 1024 + k0 + c * 8;
        else               g = Blo + (size_t)(n0 + r) * 1024 + k0 + c * 8;
        uint32_t dst = sbase + (uint32_t)(stage * STAGEB + mat * MATB + r * (LDSM*2) + c * 16);
        cp16(dst, g);
    }
    asm volatile("cp.async.commit_group;" ::: "memory");
}

__global__ __launch_bounds__(256) void mma_gemm(
    const __nv_bfloat16* __restrict__ Ahi, const __nv_bfloat16* __restrict__ Alo,
    const __nv_bfloat16* __restrict__ Bhi, const __nv_bfloat16* __restrict__ Blo,
    const float* __restrict__ bias, float* __restrict__ outF,
    __nv_bfloat16* __restrict__ outHi, __nv_bfloat16* __restrict__ outLo, int mode)
{
    extern __shared__ char sm[];
    float* sBias = (float*)(sm + 2 * STAGEB);
    const uint32_t sbase = smem_u32(sm);
    const int tid = threadIdx.x;
    const int wid = tid >> 5;
    const int m0 = blockIdx.y * 128;
    const int n0 = blockIdx.x * 128;
    const int wm = wid >> 2;
    const int wn = wid & 3;

    for (int idx = tid; idx < 16 * 128; idx += 256)
        sBias[idx] = bias[n0 + (idx & 127)];
    __syncthreads();

    FragC acc[4][2];
    #pragma unroll
    for (int i = 0; i < 4; i++)
        #pragma unroll
        for (int j = 0; j < 2; j++)
            wmma::load_matrix_sync(acc[i][j], sBias + wn*32 + j*16, 128, wmma::mem_row_major);

    issue_stage(Ahi, Alo, Bhi, Blo, sbase, 0, m0, n0, 0, tid);

    for (int kc = 0; kc < 32; kc++) {
        const int s = kc & 1;
        if (kc + 1 < 32) {
            issue_stage(Ahi, Alo, Bhi, Blo, sbase, s ^ 1, m0, n0, (kc + 1) * 32, tid);
            asm volatile("cp.async.wait_group 1;" ::: "memory");
        } else {
            asm volatile("cp.async.wait_group 0;" ::: "memory");
        }
        __syncthreads();

        const __nv_bfloat16* stg = (const __nv_bfloat16*)(sm + s * STAGEB);
        const __nv_bfloat16* sAh = stg;
        const __nv_bfloat16* sAl = stg + 128 * LDSM;
        const __nv_bfloat16* sBh = stg + 2 * 128 * LDSM;
        const __nv_bfloat16* sBl = stg + 3 * 128 * LDSM;

        #pragma unroll
        for (int ks = 0; ks < 2; ks++) {
            FragA ah[4], al[4];
            FragBc bh[2], bl[2];
            #pragma unroll
            for (int i = 0; i < 4; i++) {
                wmma::load_matrix_sync(ah[i], sAh + (wm*64 + i*16) * LDSM + ks*16, LDSM);
                wmma::load_matrix_sync(al[i], sAl + (wm*64 + i*16) * LDSM + ks*16, LDSM);
            }
            #pragma unroll
            for (int j = 0; j < 2; j++) {
                wmma::load_matrix_sync(bh[j], sBh + (wn*32 + j*16) * LDSM + ks*16, LDSM);
                wmma::load_matrix_sync(bl[j], sBl + (wn*32 + j*16) * LDSM + ks*16, LDSM);
            }
            #pragma unroll
            for (int i = 0; i < 4; i++)
                #pragma unroll
                for (int j = 0; j < 2; j++) {
                    wmma::mma_sync(acc[i][j], ah[i], bh[j], acc[i][j]);
                    wmma::mma_sync(acc[i][j], ah[i], bl[j], acc[i][j]);
                    wmma::mma_sync(acc[i][j], al[i], bh[j], acc[i][j]);
                }
        }
        __syncthreads();
    }

    if (mode == 1) {
        #pragma unroll
        for (int i = 0; i < 4; i++) {
            const int m = m0 + wm*64 + i*16;
            #pragma unroll
            for (int j = 0; j < 2; j++) {
                const int n = n0 + wn*32 + j*16;
                wmma::store_matrix_sync(outF + (size_t)m * 1024 + n, acc[i][j],
                                        1024, wmma::mem_row_major);
            }
        }
        return;
    }

    // mode 0: smem roundtrip, split to bf16 hi/lo at [b,h,s,d]
    float* sEpi = (float*)sm;
    #pragma unroll
    for (int i = 0; i < 4; i++)
        #pragma unroll
        for (int j = 0; j < 2; j++)
            wmma::store_matrix_sync(sEpi + (wm*64 + i*16) * EPLD + wn*32 + j*16,
                                    acc[i][j], EPLD, wmma::mem_row_major);
    __syncthreads();

    #pragma unroll
    for (int u = 0; u < 32; u++) {
        int e2 = u * 256 + tid;
        int r = e2 >> 6;
        int c = (e2 & 63) * 2;
        float v0 = sEpi[r * EPLD + c];
        float v1 = sEpi[r * EPLD + c + 1];
        float r0, r1;
        uint32_t hv = pack2(v0, v1, &r0, &r1);
        uint32_t lv = pack2lo(r0, r1);
        const int m = m0 + r, n = n0 + c;
        const int b = m >> 10, srow = m & 1023;
        const int h = n >> 6,  d = n & 63;
        size_t addr = ((((size_t)(b*16 + h)) * 1024 + srow) * 64 + d);
        *(uint32_t*)(outHi + addr) = hv;
        *(uint32_t*)(outLo + addr) = lv;
    }
}

// ---------------- tensor-core flash attention v3 ----------------------------
// 2 adjacent q-tiles per CTA, 8 warps (4/group), cp.async double-buffered K/V.
// O accumulator / m / l in REGISTERS; vectorized softmax (float4 LDS, u32 STS).
#define ALD 72        // bf16 tile row stride (elements); 144 bytes
#define SLD 68        // fp32 tile row stride (elements); 272 bytes
#define TQB 9216      // one 64x64 bf16 tile with ALD pad (bytes)
#define oQ   0                      // 4 tiles: [g][hi/lo]       36864
#define oKV  36864                  // 2 stages x 4 tiles        73728
#define oP   110592                 // 2 groups x {hi,lo}        36864
#define oS   147456                 // 2 groups fp32 64xSLD      34816
#define ATTN_SMEM 182272

__global__ __launch_bounds__(256) void attn_mma(
    const int* __restrict__ pad,
    __nv_bfloat16* __restrict__ Xhi, __nv_bfloat16* __restrict__ Xlo)
{
    extern __shared__ char sm[];
    const uint32_t sbase = smem_u32(sm);
    const int tid  = threadIdx.x;
    const int w    = tid >> 5, lane = tid & 31;
    const int g    = w >> 2,   wr   = w & 3;
    const int bx   = blockIdx.x;
    const int bh   = blockIdx.y;
    const int b    = bh >> 4, h = bh & 15;
    const int padb = pad[b];
    const int tlim = S_ - padb;
    const int qt   = bx * 2 + g;
    const int q0   = qt * 64;
    const size_t hoff = (size_t)bh * S_ * D_;

    float* sSg = (float*)(sm + oS + g * 17408);
    __nv_bfloat16* sPhg = (__nv_bfloat16*)(sm + oP + g * 18432);
    __nv_bfloat16* sPlg = (__nv_bfloat16*)(sm + oP + g * 18432 + TQB);
    const __nv_bfloat16* sQh = (const __nv_bfloat16*)(sm + oQ + g * 2 * TQB);
    const __nv_bfloat16* sQl = sQh + 64 * ALD;

    // preload: Q tiles (both groups, hi+lo) + K/V tile 0 into stage 0
    #pragma unroll
    for (int u = 0; u < 8; u++) {
        int c = u * 256 + tid;            // 2048 chunks
        int gm = c >> 9;                  // [g][hi/lo]
        int rc = c & 511;
        int r = rc >> 3, cc = rc & 7;
        const __nv_bfloat16* src = ((gm & 1) ? g_Qlo : g_Qhi)
            + hoff + (size_t)((bx*2 + (gm >> 1)) * 64 + r) * 64 + cc * 8;
        cp16(sbase + oQ + (uint32_t)(gm * TQB + r * 144 + cc * 16), src);
    }
    #pragma unroll
    for (int u = 0; u < 8; u++) {
        int c = u * 256 + tid;
        int mat = c >> 9;                 // Khi,Klo,Vhi,Vlo
        int rc = c & 511;
        int r = rc >> 3, cc = rc & 7;
        const __nv_bfloat16* src =
            (mat == 0 ? g_Khi : mat == 1 ? g_Klo : mat == 2 ? g_Vhi : g_Vlo)
            + hoff + (size_t)r * 64 + cc * 8;
        cp16(sbase + oKV + (uint32_t)(mat * TQB + r * 144 + cc * 16), src);
    }
    asm volatile("cp.async.commit_group;" ::: "memory");

    const int jtLast = (padb == 0) ? 15 : min(bx * 2 + 1, (tlim - 1) >> 6);

    const int lr = lane >> 1, half = lane & 1;
    const int srow = q0 + wr * 16 + lr;

    float o[32];
    #pragma unroll
    for (int c = 0; c < 32; c++) o[c] = 0.f;
    float mrow = -INFINITY, lrow = 0.f;

    for (int jt = 0; jt <= jtLast; jt++) {
        const int s = jt & 1;
        const int t0 = jt * 64;
        if (jt < jtLast) {
            const int tn = (jt + 1) * 64;
            #pragma unroll
            for (int u = 0; u < 8; u++) {
                int c = u * 256 + tid;
                int mat = c >> 9;
                int rc = c & 511;
                int r = rc >> 3, cc = rc & 7;
                const __nv_bfloat16* src =
                    (mat == 0 ? g_Khi : mat == 1 ? g_Klo : mat == 2 ? g_Vhi : g_Vlo)
                    + hoff + (size_t)(tn + r) * 64 + cc * 8;
                cp16(sbase + oKV + (uint32_t)((s ^ 1) * 36864 + mat * TQB + r * 144 + cc * 16), src);
            }
            asm volatile("cp.async.commit_group;" ::: "memory");
            asm volatile("cp.async.wait_group 1;" ::: "memory");
        } else {
            asm volatile("cp.async.wait_group 0;" ::: "memory");
        }
        __syncthreads();

        const bool act = (padb == 0) || (jt <= qt && t0 < tlim);
        if (act) {
            const __nv_bfloat16* sKh = (const __nv_bfloat16*)(sm + oKV + s * 36864);
            const __nv_bfloat16* sKl = sKh + 64 * ALD;
            const __nv_bfloat16* sVh = sKh + 2 * 64 * ALD;
            const __nv_bfloat16* sVl = sKh + 3 * 64 * ALD;

            // ---- S = Q K^T (bf16x3) ----
            {
                FragA qh[4], ql[4];
                #pragma unroll
                for (int ks = 0; ks < 4; ks++) {
                    wmma::load_matrix_sync(qh[ks], sQh + (wr*16) * ALD + ks*16, ALD);
                    wmma::load_matrix_sync(ql[ks], sQl + (wr*16) * ALD + ks*16, ALD);
                }
                FragC acc[4];
                #pragma unroll
                for (int j = 0; j < 4; j++) wmma::fill_fragment(acc[j], 0.f);
                #pragma unroll
                for (int j = 0; j < 4; j++) {
                    #pragma unroll
                    for (int ks = 0; ks < 4; ks++) {
                        FragBc kh, kl;
                        wmma::load_matrix_sync(kh, sKh + (j*16) * ALD + ks*16, ALD);
                        wmma::load_matrix_sync(kl, sKl + (j*16) * ALD + ks*16, ALD);
                        wmma::mma_sync(acc[j], qh[ks], kh, acc[j]);
                        wmma::mma_sync(acc[j], qh[ks], kl, acc[j]);
                        wmma::mma_sync(acc[j], ql[ks], kh, acc[j]);
                    }
                }
                #pragma unroll
                for (int j = 0; j < 4; j++)
                    wmma::store_matrix_sync(sSg + (wr*16) * SLD + j*16, acc[j],
                                            SLD, wmma::mem_row_major);
            }
            __syncwarp();

            // ---- softmax (regs, vectorized) ----
            float alpha;
            {
                const float4* Srow4 = (const float4*)(sSg + (wr*16 + lr) * SLD + half * 32);
                const int tbase = t0 + half * 32;
                float v[32];
                #pragma unroll
                for (int q4 = 0; q4 < 8; q4++) {
                    float4 f = Srow4[q4];
                    v[q4*4+0] = f.x; v[q4*4+1] = f.y; v[q4*4+2] = f.z; v[q4*4+3] = f.w;
                }
                float mloc = -INFINITY;
                #pragma unroll
                for (int c = 0; c < 32; c++) {
                    const int t = tbase + c;
                    float val = v[c] * 0.03125f;
                    if ((t > srow) | (t >= tlim) | (padb == 0)) val -= 1e9f;
                    v[c] = val;
                    mloc = fmaxf(mloc, val);
                }
                mloc = fmaxf(mloc, __shfl_xor_sync(0xffffffffu, mloc, 1));
                const float mnew = fmaxf(mrow, mloc);
                alpha = __expf(mrow - mnew);
                uint32_t* Pr32 = (uint32_t*)(sPhg + (wr*16 + lr) * ALD + half * 32);
                uint32_t* Pl32 = (uint32_t*)(sPlg + (wr*16 + lr) * ALD + half * 32);
                float lsum = 0.f;
                #pragma unroll
                for (int c = 0; c < 32; c += 2) {
                    float p0 = __expf(v[c]   - mnew);
                    float p1 = __expf(v[c+1] - mnew);
                    lsum += p0; lsum += p1;
                    float r0, r1;
                    Pr32[c >> 1] = pack2(p0, p1, &r0, &r1);
                    Pl32[c >> 1] = pack2lo(r0, r1);
                }
                lsum += __shfl_xor_sync(0xffffffffu, lsum, 1);
                lrow = lrow * alpha + lsum;
                mrow = mnew;
            }
            __syncwarp();

            // ---- PV (bf16x3), result overwrites S rows (warp-local) ----
            {
                FragA pfh[4], pfl[4];
                #pragma unroll
                for (int ks = 0; ks < 4; ks++) {
                    wmma::load_matrix_sync(pfh[ks], sPhg + (wr*16) * ALD + ks*16, ALD);
                    wmma::load_matrix_sync(pfl[ks], sPlg + (wr*16) * ALD + ks*16, ALD);
                }
                FragC oa[4];
                #pragma unroll
                for (int n = 0; n < 4; n++) wmma::fill_fragment(oa[n], 0.f);
                #pragma unroll
                for (int n = 0; n < 4; n++) {
                    #pragma unroll
                    for (int ks = 0; ks < 4; ks++) {
                        FragBr vh, vl;
                        wmma::load_matrix_sync(vh, sVh + (ks*16) * ALD + n*16, ALD);
                        wmma::load_matrix_sync(vl, sVl + (ks*16) * ALD + n*16, ALD);
                        wmma::mma_sync(oa[n], pfh[ks], vh, oa[n]);
                        wmma::mma_sync(oa[n], pfh[ks], vl, oa[n]);
                        wmma::mma_sync(oa[n], pfl[ks], vh, oa[n]);
                    }
                }
                #pragma unroll
                for (int n = 0; n < 4; n++)
                    wmma::store_matrix_sync(sSg + (wr*16) * SLD + n*16, oa[n],
                                            SLD, wmma::mem_row_major);
            }
            __syncwarp();

            // ---- O = O*alpha + PV (registers) ----
            {
                const float4* Pv4 = (const float4*)(sSg + (wr*16 + lr) * SLD + half * 32);
                #pragma unroll
                for (int q4 = 0; q4 < 8; q4++) {
                    float4 f = Pv4[q4];
                    o[q4*4+0] = o[q4*4+0] * alpha + f.x;
                    o[q4*4+1] = o[q4*4+1] * alpha + f.y;
                    o[q4*4+2] = o[q4*4+2] * alpha + f.z;
                    o[q4*4+3] = o[q4*4+3] * alpha + f.w;
                }
            }
        }
        __syncthreads();
    }

    // epilogue: normalize, split, store (from registers)
    {
        const float inv = 1.f / lrow;
        const size_t base = ((size_t)(b * S_ + srow)) * DM_ + h * 64 + half * 32;
        #pragma unroll
        for (int c = 0; c < 32; c += 2) {
            float v0 = o[c] * inv, v1 = o[c+1] * inv;
            float r0, r1;
            uint32_t hv = pack2(v0, v1, &r0, &r1);
            uint32_t lv = pack2lo(r0, r1);
            *(uint32_t*)(Xhi + base + c) = hv;
            *(uint32_t*)(Xlo + base + c) = lv;
        }
    }
}

// ---------------------------------------------------------------------------
extern "C" void kernel_launch(void* const* d_in, const int* in_sizes, int n_in,
                              void* d_out, int out_size)
{
    const float* Q   = (const float*)d_in[0];
    const float* K   = (const float*)d_in[1];
    const float* V   = (const float*)d_in[2];
    const int*   pad = (const int*)  d_in[3];
    const float* Wq  = (const float*)d_in[4];
    const float* bq  = (const float*)d_in[5];
    const float* Wk  = (const float*)d_in[6];
    const float* bk  = (const float*)d_in[7];
    const float* Wv  = (const float*)d_in[8];
    const float* bv  = (const float*)d_in[9];
    const float* Wo  = (const float*)d_in[10];
    const float* bo  = (const float*)d_in[11];
    float* out = (float*)d_out;

    __nv_bfloat16 *qhi, *qlo, *khi, *klo, *vhi, *vlo, *ahi, *alo, *whi, *wlo;
    cudaGetSymbolAddress((void**)&qhi, g_Qhi);
    cudaGetSymbolAddress((void**)&qlo, g_Qlo);
    cudaGetSymbolAddress((void**)&khi, g_Khi);
    cudaGetSymbolAddress((void**)&klo, g_Klo);
    cudaGetSymbolAddress((void**)&vhi, g_Vhi);
    cudaGetSymbolAddress((void**)&vlo, g_Vlo);
    cudaGetSymbolAddress((void**)&ahi, g_Ahi);
    cudaGetSymbolAddress((void**)&alo, g_Alo);
    cudaGetSymbolAddress((void**)&whi, g_Whi);
    cudaGetSymbolAddress((void**)&wlo, g_Wlo);

    cudaFuncSetAttribute(mma_gemm,
                         cudaFuncAttributeMaxDynamicSharedMemorySize, GSMEM);
    cudaFuncSetAttribute(attn_mma,
                         cudaFuncAttributeMaxDynamicSharedMemorySize, ATTN_SMEM);

    const int n4 = (B_*S_*DM_) / 4;
    const dim3 gw(32, 32), bw(32, 8);
    const dim3 gg(8, 64);

    // Q projection
    split_wT<<<gw, bw>>>(Wq, whi, wlo, 0);
    split_act<<<n4/256, 256>>>((const float4*)Q, (uint2*)ahi, (uint2*)alo, n4);
    mma_gemm<<<gg, 256, GSMEM>>>(ahi, alo, whi, wlo, bq, nullptr, qhi, qlo, 0);
    // K projection
    split_wT<<<gw, bw>>>(Wk, whi, wlo, 0);
    split_act<<<n4/256, 256>>>((const float4*)K, (uint2*)ahi, (uint2*)alo, n4);
    mma_gemm<<<gg, 256, GSMEM>>>(ahi, alo, whi, wlo, bk, nullptr, khi, klo, 0);
    // V projection
    split_wT<<<gw, bw>>>(Wv, whi, wlo, 0);
    split_act<<<n4/256, 256>>>((const float4*)V, (uint2*)ahi, (uint2*)alo, n4);
    mma_gemm<<<gg, 256, GSMEM>>>(ahi, alo, whi, wlo, bv, nullptr, vhi, vlo, 0);

    // attention -> X hi/lo into ahi/alo
    attn_mma<<<dim3(8, 128), 256, ATTN_SMEM>>>(pad, ahi, alo);

    // output projection (fp32 out)
    split_wT<<<gw, bw>>>(Wo, whi, wlo, 1);
    mma_gemm<<<gg, 256, GSMEM>>>(ahi, alo, whi, wlo, bo, out, nullptr, nullptr, 1);
}

// round 7
// speedup vs baseline: 1.2807x; 1.1535x over previous
#include <cuda_runtime.h>
#include <cuda_bf16.h>
#include <mma.h>
#include <math.h>
#include <stdint.h>

using namespace nvcuda;

#define S_   1024
#define DM_  1024
#define B_   8
#define H_   16
#define D_   64

// ---------------- scratch (__device__ globals; no allocation) ----------------
__device__ __nv_bfloat16 g_Qhi[B_*H_*S_*D_];  // [b,h,s,d]
__device__ __nv_bfloat16 g_Qlo[B_*H_*S_*D_];
__device__ __nv_bfloat16 g_Khi[B_*H_*S_*D_];
__device__ __nv_bfloat16 g_Klo[B_*H_*S_*D_];
__device__ __nv_bfloat16 g_Vhi[B_*H_*S_*D_];
__device__ __nv_bfloat16 g_Vlo[B_*H_*S_*D_];
__device__ __nv_bfloat16 g_Ahi[B_*S_*DM_];    // activation hi/lo (inputs, then X)
__device__ __nv_bfloat16 g_Alo[B_*S_*DM_];
__device__ __nv_bfloat16 g_Whi[DM_*DM_];      // weight-transposed hi/lo [N][K]
__device__ __nv_bfloat16 g_Wlo[DM_*DM_];

// ---------------- helpers ----------------
__device__ __forceinline__ uint32_t smem_u32(const void* p) {
    uint32_t a;
    asm("{ .reg .u64 t; cvta.to.shared.u64 t, %1; cvt.u32.u64 %0, t; }"
        : "=r"(a) : "l"(p));
    return a;
}
__device__ __forceinline__ void cp16(uint32_t dst, const void* src) {
    asm volatile("cp.async.cg.shared.global [%0], [%1], 16;" :: "r"(dst), "l"(src));
}
__device__ __forceinline__ uint32_t pack2(float a, float b, float* ra, float* rb) {
    __nv_bfloat16 ha = __float2bfloat16(a), hb = __float2bfloat16(b);
    *ra = a - __bfloat162float(ha);
    *rb = b - __bfloat162float(hb);
    return (uint32_t)__bfloat16_as_ushort(ha) |
           ((uint32_t)__bfloat16_as_ushort(hb) << 16);
}
__device__ __forceinline__ uint32_t pack2lo(float a, float b) {
    __nv_bfloat16 ha = __float2bfloat16(a), hb = __float2bfloat16(b);
    return (uint32_t)__bfloat16_as_ushort(ha) |
           ((uint32_t)__bfloat16_as_ushort(hb) << 16);
}

// ---------------- conversion kernels ----------------
__global__ __launch_bounds__(256) void split_act(
    const float4* __restrict__ src, uint2* __restrict__ hi, uint2* __restrict__ lo, int n4)
{
    int i = blockIdx.x * 256 + threadIdx.x;
    if (i >= n4) return;
    float4 v = src[i];
    float rx, ry, rz, rw;
    uint2 h, l;
    h.x = pack2(v.x, v.y, &rx, &ry);
    h.y = pack2(v.z, v.w, &rz, &rw);
    l.x = pack2lo(rx, ry);
    l.y = pack2lo(rz, rw);
    hi[i] = h; lo[i] = l;
}

// weight transpose+split: out[n][k]; mode0 src=W[h][k][d] (n=h*64+d), mode1 src=Wo[k][n]
__global__ __launch_bounds__(256) void split_wT(
    const float* __restrict__ W, __nv_bfloat16* __restrict__ hi,
    __nv_bfloat16* __restrict__ lo, int mode)
{
    __shared__ float t[32][33];
    int k0 = blockIdx.x * 32, n0 = blockIdx.y * 32;
    int tx = threadIdx.x, ty = threadIdx.y;   // 32 x 8
    #pragma unroll
    for (int i = 0; i < 4; i++) {
        int k = k0 + ty + 8*i, n = n0 + tx;
        float v = mode ? W[(size_t)k * 1024 + n]
                       : W[(((size_t)(n >> 6)) * 1024 + k) * 64 + (n & 63)];
        t[ty + 8*i][tx] = v;
    }
    __syncthreads();
    #pragma unroll
    for (int i = 0; i < 4; i++) {
        int n = n0 + ty + 8*i, k = k0 + tx;
        float v = t[tx][ty + 8*i];
        __nv_bfloat16 h = __float2bfloat16(v);
        __nv_bfloat16 l = __float2bfloat16(v - __bfloat162float(h));
        hi[(size_t)n * 1024 + k] = h;
        lo[(size_t)n * 1024 + k] = l;
    }
}

// ---------------- wmma GEMM (bf16x3 emulated fp32) ----------------
// CTA tile 128x128, 4 warps (2x2), warp tile 64x64, BK=32, double-buffered.
#define LDSM   40
#define MATB   (128 * LDSM * 2)
#define STAGEB (4 * MATB)
#define GSMEM  (2 * STAGEB + 16 * 128 * 4)
#define EPLD   132

typedef wmma::fragment<wmma::matrix_a, 16,16,16, __nv_bfloat16, wmma::row_major> FragA;
typedef wmma::fragment<wmma::matrix_b, 16,16,16, __nv_bfloat16, wmma::col_major> FragBc;
typedef wmma::fragment<wmma::matrix_b, 16,16,16, __nv_bfloat16, wmma::row_major> FragBr;
typedef wmma::fragment<wmma::accumulator, 16,16,16, float> FragC;

__device__ __forceinline__ void issue_stage(
    const __nv_bfloat16* __restrict__ Ahi, const __nv_bfloat16* __restrict__ Alo,
    const __nv_bfloat16* __restrict__ Bhi, const __nv_bfloat16* __restrict__ Blo,
    uint32_t sbase, int stage, int m0, int n0, int k0, int tid)
{
    #pragma unroll
    for (int u = 0; u < 16; u++) {
        int chunk = u * 128 + tid;         // 2048 chunks of 16B
        int mat = chunk >> 9;
        int r   = (chunk >> 2) & 127;
        int c   = chunk & 3;
        const __nv_bfloat16* g;
        if      (mat == 0) g = Ahi + (size_t)(m0 + r) * 1024 + k0 + c * 8;
        else if (mat == 1) g = Alo + (size_t)(m0 + r) * 1024 + k0 + c * 8;
        else if (mat == 2) g = Bhi + (size_t)(n0 + r) * 1024 + k0 + c * 8;
        else               g = Blo + (size_t)(n0 + r) * 1024 + k0 + c * 8;
        uint32_t dst = sbase + (uint32_t)(stage * STAGEB + mat * MATB + r * (LDSM*2) + c * 16);
        cp16(dst, g);
    }
    asm volatile("cp.async.commit_group;" ::: "memory");
}

__global__ __launch_bounds__(128, 2) void mma_gemm(
    const __nv_bfloat16* __restrict__ Ahi, const __nv_bfloat16* __restrict__ Alo,
    const __nv_bfloat16* __restrict__ Bhi, const __nv_bfloat16* __restrict__ Blo,
    const float* __restrict__ bias, float* __restrict__ outF,
    __nv_bfloat16* __restrict__ outHi, __nv_bfloat16* __restrict__ outLo, int mode)
{
    extern __shared__ char sm[];
    float* sBias = (float*)(sm + 2 * STAGEB);
    const uint32_t sbase = smem_u32(sm);
    const int tid = threadIdx.x;
    const int wid = tid >> 5;
    const int m0 = blockIdx.y * 128;
    const int n0 = blockIdx.x * 128;
    const int wm = wid >> 1;     // 0..1
    const int wn = wid & 1;      // 0..1

    for (int idx = tid; idx < 16 * 128; idx += 128)
        sBias[idx] = bias[n0 + (idx & 127)];
    __syncthreads();

    FragC acc[4][4];
    #pragma unroll
    for (int i = 0; i < 4; i++)
        #pragma unroll
        for (int j = 0; j < 4; j++)
            wmma::load_matrix_sync(acc[i][j], sBias + wn*64 + j*16, 128, wmma::mem_row_major);

    issue_stage(Ahi, Alo, Bhi, Blo, sbase, 0, m0, n0, 0, tid);

    for (int kc = 0; kc < 32; kc++) {
        const int s = kc & 1;
        if (kc + 1 < 32) {
            issue_stage(Ahi, Alo, Bhi, Blo, sbase, s ^ 1, m0, n0, (kc + 1) * 32, tid);
            asm volatile("cp.async.wait_group 1;" ::: "memory");
        } else {
            asm volatile("cp.async.wait_group 0;" ::: "memory");
        }
        __syncthreads();

        const __nv_bfloat16* stg = (const __nv_bfloat16*)(sm + s * STAGEB);
        const __nv_bfloat16* sAh = stg;
        const __nv_bfloat16* sAl = stg + 128 * LDSM;
        const __nv_bfloat16* sBh = stg + 2 * 128 * LDSM;
        const __nv_bfloat16* sBl = stg + 3 * 128 * LDSM;

        #pragma unroll
        for (int ks = 0; ks < 2; ks++) {
            FragA ah[4], al[4];
            FragBc bh[4], bl[4];
            #pragma unroll
            for (int i = 0; i < 4; i++) {
                wmma::load_matrix_sync(ah[i], sAh + (wm*64 + i*16) * LDSM + ks*16, LDSM);
                wmma::load_matrix_sync(al[i], sAl + (wm*64 + i*16) * LDSM + ks*16, LDSM);
            }
            #pragma unroll
            for (int j = 0; j < 4; j++) {
                wmma::load_matrix_sync(bh[j], sBh + (wn*64 + j*16) * LDSM + ks*16, LDSM);
                wmma::load_matrix_sync(bl[j], sBl + (wn*64 + j*16) * LDSM + ks*16, LDSM);
            }
            #pragma unroll
            for (int i = 0; i < 4; i++)
                #pragma unroll
                for (int j = 0; j < 4; j++) {
                    wmma::mma_sync(acc[i][j], ah[i], bh[j], acc[i][j]);
                    wmma::mma_sync(acc[i][j], ah[i], bl[j], acc[i][j]);
                    wmma::mma_sync(acc[i][j], al[i], bh[j], acc[i][j]);
                }
        }
        __syncthreads();
    }

    if (mode == 1) {
        #pragma unroll
        for (int i = 0; i < 4; i++) {
            const int m = m0 + wm*64 + i*16;
            #pragma unroll
            for (int j = 0; j < 4; j++) {
                const int n = n0 + wn*64 + j*16;
                wmma::store_matrix_sync(outF + (size_t)m * 1024 + n, acc[i][j],
                                        1024, wmma::mem_row_major);
            }
        }
        return;
    }

    // mode 0: smem roundtrip, split to bf16 hi/lo at [b,h,s,d]
    float* sEpi = (float*)sm;
    #pragma unroll
    for (int i = 0; i < 4; i++)
        #pragma unroll
        for (int j = 0; j < 4; j++)
            wmma::store_matrix_sync(sEpi + (wm*64 + i*16) * EPLD + wn*64 + j*16,
                                    acc[i][j], EPLD, wmma::mem_row_major);
    __syncthreads();

    #pragma unroll
    for (int u = 0; u < 64; u++) {
        int e2 = u * 128 + tid;
        int r = e2 >> 6;
        int c = (e2 & 63) * 2;
        float v0 = sEpi[r * EPLD + c];
        float v1 = sEpi[r * EPLD + c + 1];
        float r0, r1;
        uint32_t hv = pack2(v0, v1, &r0, &r1);
        uint32_t lv = pack2lo(r0, r1);
        const int m = m0 + r, n = n0 + c;
        const int b = m >> 10, srow = m & 1023;
        const int h = n >> 6,  d = n & 63;
        size_t addr = ((((size_t)(b*16 + h)) * 1024 + srow) * 64 + d);
        *(uint32_t*)(outHi + addr) = hv;
        *(uint32_t*)(outLo + addr) = lv;
    }
}

// ---------------- tensor-core flash attention v3 ----------------------------
// 2 adjacent q-tiles per CTA, 8 warps (4/group), cp.async double-buffered K/V.
// O accumulator / m / l in REGISTERS; vectorized softmax (float4 LDS, u32 STS).
#define ALD 72        // bf16 tile row stride (elements); 144 bytes
#define SLD 68        // fp32 tile row stride (elements); 272 bytes
#define TQB 9216      // one 64x64 bf16 tile with ALD pad (bytes)
#define oQ   0                      // 4 tiles: [g][hi/lo]       36864
#define oKV  36864                  // 2 stages x 4 tiles        73728
#define oP   110592                 // 2 groups x {hi,lo}        36864
#define oS   147456                 // 2 groups fp32 64xSLD      34816
#define ATTN_SMEM 182272

__global__ __launch_bounds__(256) void attn_mma(
    const int* __restrict__ pad,
    __nv_bfloat16* __restrict__ Xhi, __nv_bfloat16* __restrict__ Xlo)
{
    extern __shared__ char sm[];
    const uint32_t sbase = smem_u32(sm);
    const int tid  = threadIdx.x;
    const int w    = tid >> 5, lane = tid & 31;
    const int g    = w >> 2,   wr   = w & 3;
    const int bx   = blockIdx.x;
    const int bh   = blockIdx.y;
    const int b    = bh >> 4, h = bh & 15;
    const int padb = pad[b];
    const int tlim = S_ - padb;
    const int qt   = bx * 2 + g;
    const int q0   = qt * 64;
    const size_t hoff = (size_t)bh * S_ * D_;

    float* sSg = (float*)(sm + oS + g * 17408);
    __nv_bfloat16* sPhg = (__nv_bfloat16*)(sm + oP + g * 18432);
    __nv_bfloat16* sPlg = (__nv_bfloat16*)(sm + oP + g * 18432 + TQB);
    const __nv_bfloat16* sQh = (const __nv_bfloat16*)(sm + oQ + g * 2 * TQB);
    const __nv_bfloat16* sQl = sQh + 64 * ALD;

    // preload: Q tiles (both groups, hi+lo) + K/V tile 0 into stage 0
    #pragma unroll
    for (int u = 0; u < 8; u++) {
        int c = u * 256 + tid;            // 2048 chunks
        int gm = c >> 9;                  // [g][hi/lo]
        int rc = c & 511;
        int r = rc >> 3, cc = rc & 7;
        const __nv_bfloat16* src = ((gm & 1) ? g_Qlo : g_Qhi)
            + hoff + (size_t)((bx*2 + (gm >> 1)) * 64 + r) * 64 + cc * 8;
        cp16(sbase + oQ + (uint32_t)(gm * TQB + r * 144 + cc * 16), src);
    }
    #pragma unroll
    for (int u = 0; u < 8; u++) {
        int c = u * 256 + tid;
        int mat = c >> 9;                 // Khi,Klo,Vhi,Vlo
        int rc = c & 511;
        int r = rc >> 3, cc = rc & 7;
        const __nv_bfloat16* src =
            (mat == 0 ? g_Khi : mat == 1 ? g_Klo : mat == 2 ? g_Vhi : g_Vlo)
            + hoff + (size_t)r * 64 + cc * 8;
        cp16(sbase + oKV + (uint32_t)(mat * TQB + r * 144 + cc * 16), src);
    }
    asm volatile("cp.async.commit_group;" ::: "memory");

    const int jtLast = (padb == 0) ? 15 : min(bx * 2 + 1, (tlim - 1) >> 6);

    const int lr = lane >> 1, half = lane & 1;
    const int srow = q0 + wr * 16 + lr;

    float o[32];
    #pragma unroll
    for (int c = 0; c < 32; c++) o[c] = 0.f;
    float mrow = -INFINITY, lrow = 0.f;

    for (int jt = 0; jt <= jtLast; jt++) {
        const int s = jt & 1;
        const int t0 = jt * 64;
        if (jt < jtLast) {
            const int tn = (jt + 1) * 64;
            #pragma unroll
            for (int u = 0; u < 8; u++) {
                int c = u * 256 + tid;
                int mat = c >> 9;
                int rc = c & 511;
                int r = rc >> 3, cc = rc & 7;
                const __nv_bfloat16* src =
                    (mat == 0 ? g_Khi : mat == 1 ? g_Klo : mat == 2 ? g_Vhi : g_Vlo)
                    + hoff + (size_t)(tn + r) * 64 + cc * 8;
                cp16(sbase + oKV + (uint32_t)((s ^ 1) * 36864 + mat * TQB + r * 144 + cc * 16), src);
            }
            asm volatile("cp.async.commit_group;" ::: "memory");
            asm volatile("cp.async.wait_group 1;" ::: "memory");
        } else {
            asm volatile("cp.async.wait_group 0;" ::: "memory");
        }
        __syncthreads();

        const bool act = (padb == 0) || (jt <= qt && t0 < tlim);
        if (act) {
            const __nv_bfloat16* sKh = (const __nv_bfloat16*)(sm + oKV + s * 36864);
            const __nv_bfloat16* sKl = sKh + 64 * ALD;
            const __nv_bfloat16* sVh = sKh + 2 * 64 * ALD;
            const __nv_bfloat16* sVl = sKh + 3 * 64 * ALD;

            // ---- S = Q K^T (bf16x3) ----
            {
                FragA qh[4], ql[4];
                #pragma unroll
                for (int ks = 0; ks < 4; ks++) {
                    wmma::load_matrix_sync(qh[ks], sQh + (wr*16) * ALD + ks*16, ALD);
                    wmma::load_matrix_sync(ql[ks], sQl + (wr*16) * ALD + ks*16, ALD);
                }
                FragC acc[4];
                #pragma unroll
                for (int j = 0; j < 4; j++) wmma::fill_fragment(acc[j], 0.f);
                #pragma unroll
                for (int j = 0; j < 4; j++) {
                    #pragma unroll
                    for (int ks = 0; ks < 4; ks++) {
                        FragBc kh, kl;
                        wmma::load_matrix_sync(kh, sKh + (j*16) * ALD + ks*16, ALD);
                        wmma::load_matrix_sync(kl, sKl + (j*16) * ALD + ks*16, ALD);
                        wmma::mma_sync(acc[j], qh[ks], kh, acc[j]);
                        wmma::mma_sync(acc[j], qh[ks], kl, acc[j]);
                        wmma::mma_sync(acc[j], ql[ks], kh, acc[j]);
                    }
                }
                #pragma unroll
                for (int j = 0; j < 4; j++)
                    wmma::store_matrix_sync(sSg + (wr*16) * SLD + j*16, acc[j],
                                            SLD, wmma::mem_row_major);
            }
            __syncwarp();

            // ---- softmax (regs, vectorized) ----
            float alpha;
            {
                const float4* Srow4 = (const float4*)(sSg + (wr*16 + lr) * SLD + half * 32);
                const int tbase = t0 + half * 32;
                float v[32];
                #pragma unroll
                for (int q4 = 0; q4 < 8; q4++) {
                    float4 f = Srow4[q4];
                    v[q4*4+0] = f.x; v[q4*4+1] = f.y; v[q4*4+2] = f.z; v[q4*4+3] = f.w;
                }
                float mloc = -INFINITY;
                #pragma unroll
                for (int c = 0; c < 32; c++) {
                    const int t = tbase + c;
                    float val = v[c] * 0.03125f;
                    if ((t > srow) | (t >= tlim) | (padb == 0)) val -= 1e9f;
                    v[c] = val;
                    mloc = fmaxf(mloc, val);
                }
                mloc = fmaxf(mloc, __shfl_xor_sync(0xffffffffu, mloc, 1));
                const float mnew = fmaxf(mrow, mloc);
                alpha = __expf(mrow - mnew);
                uint32_t* Pr32 = (uint32_t*)(sPhg + (wr*16 + lr) * ALD + half * 32);
                uint32_t* Pl32 = (uint32_t*)(sPlg + (wr*16 + lr) * ALD + half * 32);
                float lsum = 0.f;
                #pragma unroll
                for (int c = 0; c < 32; c += 2) {
                    float p0 = __expf(v[c]   - mnew);
                    float p1 = __expf(v[c+1] - mnew);
                    lsum += p0; lsum += p1;
                    float r0, r1;
                    Pr32[c >> 1] = pack2(p0, p1, &r0, &r1);
                    Pl32[c >> 1] = pack2lo(r0, r1);
                }
                lsum += __shfl_xor_sync(0xffffffffu, lsum, 1);
                lrow = lrow * alpha + lsum;
                mrow = mnew;
            }
            __syncwarp();

            // ---- PV (bf16x3), result overwrites S rows (warp-local) ----
            {
                FragA pfh[4], pfl[4];
                #pragma unroll
                for (int ks = 0; ks < 4; ks++) {
                    wmma::load_matrix_sync(pfh[ks], sPhg + (wr*16) * ALD + ks*16, ALD);
                    wmma::load_matrix_sync(pfl[ks], sPlg + (wr*16) * ALD + ks*16, ALD);
                }
                FragC oa[4];
                #pragma unroll
                for (int n = 0; n < 4; n++) wmma::fill_fragment(oa[n], 0.f);
                #pragma unroll
                for (int n = 0; n < 4; n++) {
                    #pragma unroll
                    for (int ks = 0; ks < 4; ks++) {
                        FragBr vh, vl;
                        wmma::load_matrix_sync(vh, sVh + (ks*16) * ALD + n*16, ALD);
                        wmma::load_matrix_sync(vl, sVl + (ks*16) * ALD + n*16, ALD);
                        wmma::mma_sync(oa[n], pfh[ks], vh, oa[n]);
                        wmma::mma_sync(oa[n], pfh[ks], vl, oa[n]);
                        wmma::mma_sync(oa[n], pfl[ks], vh, oa[n]);
                    }
                }
                #pragma unroll
                for (int n = 0; n < 4; n++)
                    wmma::store_matrix_sync(sSg + (wr*16) * SLD + n*16, oa[n],
                                            SLD, wmma::mem_row_major);
            }
            __syncwarp();

            // ---- O = O*alpha + PV (registers) ----
            {
                const float4* Pv4 = (const float4*)(sSg + (wr*16 + lr) * SLD + half * 32);
                #pragma unroll
                for (int q4 = 0; q4 < 8; q4++) {
                    float4 f = Pv4[q4];
                    o[q4*4+0] = o[q4*4+0] * alpha + f.x;
                    o[q4*4+1] = o[q4*4+1] * alpha + f.y;
                    o[q4*4+2] = o[q4*4+2] * alpha + f.z;
                    o[q4*4+3] = o[q4*4+3] * alpha + f.w;
                }
            }
        }
        __syncthreads();
    }

    // epilogue: normalize, split, store (from registers)
    {
        const float inv = 1.f / lrow;
        const size_t base = ((size_t)(b * S_ + srow)) * DM_ + h * 64 + half * 32;
        #pragma unroll
        for (int c = 0; c < 32; c += 2) {
            float v0 = o[c] * inv, v1 = o[c+1] * inv;
            float r0, r1;
            uint32_t hv = pack2(v0, v1, &r0, &r1);
            uint32_t lv = pack2lo(r0, r1);
            *(uint32_t*)(Xhi + base + c) = hv;
            *(uint32_t*)(Xlo + base + c) = lv;
        }
    }
}

// ---------------------------------------------------------------------------
extern "C" void kernel_launch(void* const* d_in, const int* in_sizes, int n_in,
                              void* d_out, int out_size)
{
    const float* Q   = (const float*)d_in[0];
    const float* K   = (const float*)d_in[1];
    const float* V   = (const float*)d_in[2];
    const int*   pad = (const int*)  d_in[3];
    const float* Wq  = (const float*)d_in[4];
    const float* bq  = (const float*)d_in[5];
    const float* Wk  = (const float*)d_in[6];
    const float* bk  = (const float*)d_in[7];
    const float* Wv  = (const float*)d_in[8];
    const float* bv  = (const float*)d_in[9];
    const float* Wo  = (const float*)d_in[10];
    const float* bo  = (const float*)d_in[11];
    float* out = (float*)d_out;

    __nv_bfloat16 *qhi, *qlo, *khi, *klo, *vhi, *vlo, *ahi, *alo, *whi, *wlo;
    cudaGetSymbolAddress((void**)&qhi, g_Qhi);
    cudaGetSymbolAddress((void**)&qlo, g_Qlo);
    cudaGetSymbolAddress((void**)&khi, g_Khi);
    cudaGetSymbolAddress((void**)&klo, g_Klo);
    cudaGetSymbolAddress((void**)&vhi, g_Vhi);
    cudaGetSymbolAddress((void**)&vlo, g_Vlo);
    cudaGetSymbolAddress((void**)&ahi, g_Ahi);
    cudaGetSymbolAddress((void**)&alo, g_Alo);
    cudaGetSymbolAddress((void**)&whi, g_Whi);
    cudaGetSymbolAddress((void**)&wlo, g_Wlo);

    cudaFuncSetAttribute(mma_gemm,
                         cudaFuncAttributeMaxDynamicSharedMemorySize, GSMEM);
    cudaFuncSetAttribute(attn_mma,
                         cudaFuncAttributeMaxDynamicSharedMemorySize, ATTN_SMEM);

    const int n4 = (B_*S_*DM_) / 4;
    const dim3 gw(32, 32), bw(32, 8);
    const dim3 gg(8, 64);

    // Q projection
    split_wT<<<gw, bw>>>(Wq, whi, wlo, 0);
    split_act<<<n4/256, 256>>>((const float4*)Q, (uint2*)ahi, (uint2*)alo, n4);
    mma_gemm<<<gg, 128, GSMEM>>>(ahi, alo, whi, wlo, bq, nullptr, qhi, qlo, 0);
    // K projection
    split_wT<<<gw, bw>>>(Wk, whi, wlo, 0);
    split_act<<<n4/256, 256>>>((const float4*)K, (uint2*)ahi, (uint2*)alo, n4);
    mma_gemm<<<gg, 128, GSMEM>>>(ahi, alo, whi, wlo, bk, nullptr, khi, klo, 0);
    // V projection
    split_wT<<<gw, bw>>>(Wv, whi, wlo, 0);
    split_act<<<n4/256, 256>>>((const float4*)V, (uint2*)ahi, (uint2*)alo, n4);
    mma_gemm<<<gg, 128, GSMEM>>>(ahi, alo, whi, wlo, bv, nullptr, vhi, vlo, 0);

    // attention -> X hi/lo into ahi/alo
    attn_mma<<<dim3(8, 128), 256, ATTN_SMEM>>>(pad, ahi, alo);

    // output projection (fp32 out)
    split_wT<<<gw, bw>>>(Wo, whi, wlo, 1);
    mma_gemm<<<gg, 128, GSMEM>>>(ahi, alo, whi, wlo, bo, out, nullptr, nullptr, 1);
}

// round 8
// speedup vs baseline: 1.4509x; 1.1329x over previous
#include <cuda_runtime.h>
#include <cuda_bf16.h>
#include <cuda_fp16.h>
#include <mma.h>
#include <math.h>
#include <stdint.h>

using namespace nvcuda;

#define S_   1024
#define DM_  1024
#define B_   8
#define H_   16
#define D_   64

// ---------------- scratch (__device__ globals; no allocation) ----------------
__device__ __nv_bfloat16 g_Qhi[B_*H_*S_*D_];  // [b,h,s,d]
__device__ __nv_bfloat16 g_Qlo[B_*H_*S_*D_];
__device__ __nv_bfloat16 g_Khi[B_*H_*S_*D_];
__device__ __nv_bfloat16 g_Klo[B_*H_*S_*D_];
__device__ __nv_bfloat16 g_Vhi[B_*H_*S_*D_];
__device__ __nv_bfloat16 g_Vlo[B_*H_*S_*D_];
__device__ __nv_bfloat16 g_Ahi[B_*S_*DM_];    // activation hi/lo (inputs, then X)
__device__ __nv_bfloat16 g_Alo[B_*S_*DM_];
__device__ __nv_bfloat16 g_Whi[DM_*DM_];      // weight-transposed hi/lo [N][K]
__device__ __nv_bfloat16 g_Wlo[DM_*DM_];

// ---------------- helpers ----------------
__device__ __forceinline__ uint32_t smem_u32(const void* p) {
    uint32_t a;
    asm("{ .reg .u64 t; cvta.to.shared.u64 t, %1; cvt.u32.u64 %0, t; }"
        : "=r"(a) : "l"(p));
    return a;
}
__device__ __forceinline__ void cp16(uint32_t dst, const void* src) {
    asm volatile("cp.async.cg.shared.global [%0], [%1], 16;" :: "r"(dst), "l"(src));
}
__device__ __forceinline__ uint32_t pack2(float a, float b, float* ra, float* rb) {
    __nv_bfloat16 ha = __float2bfloat16(a), hb = __float2bfloat16(b);
    *ra = a - __bfloat162float(ha);
    *rb = b - __bfloat162float(hb);
    return (uint32_t)__bfloat16_as_ushort(ha) |
           ((uint32_t)__bfloat16_as_ushort(hb) << 16);
}
__device__ __forceinline__ uint32_t pack2lo(float a, float b) {
    __nv_bfloat16 ha = __float2bfloat16(a), hb = __float2bfloat16(b);
    return (uint32_t)__bfloat16_as_ushort(ha) |
           ((uint32_t)__bfloat16_as_ushort(hb) << 16);
}
__device__ __forceinline__ uint32_t pack2h(float a, float b, float* ra, float* rb) {
    __half ha = __float2half_rn(a), hb = __float2half_rn(b);
    *ra = a - __half2float(ha);
    *rb = b - __half2float(hb);
    return (uint32_t)__half_as_ushort(ha) |
           ((uint32_t)__half_as_ushort(hb) << 16);
}
__device__ __forceinline__ uint32_t pack2hlo(float a, float b) {
    __half ha = __float2half_rn(a), hb = __float2half_rn(b);
    return (uint32_t)__half_as_ushort(ha) |
           ((uint32_t)__half_as_ushort(hb) << 16);
}

// ---------------- conversion kernels ----------------
__global__ __launch_bounds__(256) void split_act(
    const float4* __restrict__ src, uint2* __restrict__ hi, uint2* __restrict__ lo, int n4)
{
    int i = blockIdx.x * 256 + threadIdx.x;
    if (i >= n4) return;
    float4 v = src[i];
    float rx, ry, rz, rw;
    uint2 h, l;
    h.x = pack2(v.x, v.y, &rx, &ry);
    h.y = pack2(v.z, v.w, &rz, &rw);
    l.x = pack2lo(rx, ry);
    l.y = pack2lo(rz, rw);
    hi[i] = h; lo[i] = l;
}

__global__ __launch_bounds__(256) void split_act_h(
    const float4* __restrict__ src, uint2* __restrict__ hi, uint2* __restrict__ lo, int n4)
{
    int i = blockIdx.x * 256 + threadIdx.x;
    if (i >= n4) return;
    float4 v = src[i];
    float rx, ry, rz, rw;
    uint2 h, l;
    h.x = pack2h(v.x, v.y, &rx, &ry);
    h.y = pack2h(v.z, v.w, &rz, &rw);
    l.x = pack2hlo(rx, ry);
    l.y = pack2hlo(rz, rw);
    hi[i] = h; lo[i] = l;
}

// weight transpose+split bf16: out[n][k]; mode0 src=W[h][k][d], mode1 src=Wo[k][n]
__global__ __launch_bounds__(256) void split_wT(
    const float* __restrict__ W, __nv_bfloat16* __restrict__ hi,
    __nv_bfloat16* __restrict__ lo, int mode)
{
    __shared__ float t[32][33];
    int k0 = blockIdx.x * 32, n0 = blockIdx.y * 32;
    int tx = threadIdx.x, ty = threadIdx.y;   // 32 x 8
    #pragma unroll
    for (int i = 0; i < 4; i++) {
        int k = k0 + ty + 8*i, n = n0 + tx;
        float v = mode ? W[(size_t)k * 1024 + n]
                       : W[(((size_t)(n >> 6)) * 1024 + k) * 64 + (n & 63)];
        t[ty + 8*i][tx] = v;
    }
    __syncthreads();
    #pragma unroll
    for (int i = 0; i < 4; i++) {
        int n = n0 + ty + 8*i, k = k0 + tx;
        float v = t[tx][ty + 8*i];
        __nv_bfloat16 h = __float2bfloat16(v);
        __nv_bfloat16 l = __float2bfloat16(v - __bfloat162float(h));
        hi[(size_t)n * 1024 + k] = h;
        lo[(size_t)n * 1024 + k] = l;
    }
}

// weight transpose, fp16 hi only (2-pass GEMM never needs W-lo): src=W[h][k][d]
__global__ __launch_bounds__(256) void split_wT_h(
    const float* __restrict__ W, __half* __restrict__ hi)
{
    __shared__ float t[32][33];
    int k0 = blockIdx.x * 32, n0 = blockIdx.y * 32;
    int tx = threadIdx.x, ty = threadIdx.y;
    #pragma unroll
    for (int i = 0; i < 4; i++) {
        int k = k0 + ty + 8*i, n = n0 + tx;
        t[ty + 8*i][tx] = W[(((size_t)(n >> 6)) * 1024 + k) * 64 + (n & 63)];
    }
    __syncthreads();
    #pragma unroll
    for (int i = 0; i < 4; i++) {
        int n = n0 + ty + 8*i, k = k0 + tx;
        hi[(size_t)n * 1024 + k] = __float2half_rn(t[tx][ty + 8*i]);
    }
}

// ---------------- fragment typedefs ----------------
#define LDSM   40
#define MATB   (128 * LDSM * 2)
#define STAGEB (4 * MATB)
#define GSMEM  (2 * STAGEB + 16 * 128 * 4)
#define STAGEBH (3 * MATB)
#define GSMEMH  (2 * STAGEBH + 16 * 128 * 4)
#define EPLD   132

typedef wmma::fragment<wmma::matrix_a, 16,16,16, __nv_bfloat16, wmma::row_major> FragA;
typedef wmma::fragment<wmma::matrix_b, 16,16,16, __nv_bfloat16, wmma::col_major> FragBc;
typedef wmma::fragment<wmma::matrix_b, 16,16,16, __nv_bfloat16, wmma::row_major> FragBr;
typedef wmma::fragment<wmma::matrix_a, 16,16,16, __half, wmma::row_major> HFragA;
typedef wmma::fragment<wmma::matrix_b, 16,16,16, __half, wmma::col_major> HFragB;
typedef wmma::fragment<wmma::accumulator, 16,16,16, float> FragC;

// ---------------- bf16x3 GEMM (V proj + out proj) ----------------
__device__ __forceinline__ void issue_stage(
    const __nv_bfloat16* __restrict__ Ahi, const __nv_bfloat16* __restrict__ Alo,
    const __nv_bfloat16* __restrict__ Bhi, const __nv_bfloat16* __restrict__ Blo,
    uint32_t sbase, int stage, int m0, int n0, int k0, int tid)
{
    #pragma unroll
    for (int u = 0; u < 16; u++) {
        int chunk = u * 128 + tid;
        int mat = chunk >> 9;
        int r   = (chunk >> 2) & 127;
        int c   = chunk & 3;
        const __nv_bfloat16* g;
        if      (mat == 0) g = Ahi + (size_t)(m0 + r) * 1024 + k0 + c * 8;
        else if (mat == 1) g = Alo + (size_t)(m0 + r) * 1024 + k0 + c * 8;
        else if (mat == 2) g = Bhi + (size_t)(n0 + r) * 1024 + k0 + c * 8;
        else               g = Blo + (size_t)(n0 + r) * 1024 + k0 + c * 8;
        uint32_t dst = sbase + (uint32_t)(stage * STAGEB + mat * MATB + r * (LDSM*2) + c * 16);
        cp16(dst, g);
    }
    asm volatile("cp.async.commit_group;" ::: "memory");
}

__global__ __launch_bounds__(128, 2) void mma_gemm(
    const __nv_bfloat16* __restrict__ Ahi, const __nv_bfloat16* __restrict__ Alo,
    const __nv_bfloat16* __restrict__ Bhi, const __nv_bfloat16* __restrict__ Blo,
    const float* __restrict__ bias, float* __restrict__ outF,
    __nv_bfloat16* __restrict__ outHi, __nv_bfloat16* __restrict__ outLo, int mode)
{
    extern __shared__ char sm[];
    float* sBias = (float*)(sm + 2 * STAGEB);
    const uint32_t sbase = smem_u32(sm);
    const int tid = threadIdx.x;
    const int wid = tid >> 5;
    const int m0 = blockIdx.y * 128;
    const int n0 = blockIdx.x * 128;
    const int wm = wid >> 1;
    const int wn = wid & 1;

    for (int idx = tid; idx < 16 * 128; idx += 128)
        sBias[idx] = bias[n0 + (idx & 127)];
    __syncthreads();

    FragC acc[4][4];
    #pragma unroll
    for (int i = 0; i < 4; i++)
        #pragma unroll
        for (int j = 0; j < 4; j++)
            wmma::load_matrix_sync(acc[i][j], sBias + wn*64 + j*16, 128, wmma::mem_row_major);

    issue_stage(Ahi, Alo, Bhi, Blo, sbase, 0, m0, n0, 0, tid);

    for (int kc = 0; kc < 32; kc++) {
        const int s = kc & 1;
        if (kc + 1 < 32) {
            issue_stage(Ahi, Alo, Bhi, Blo, sbase, s ^ 1, m0, n0, (kc + 1) * 32, tid);
            asm volatile("cp.async.wait_group 1;" ::: "memory");
        } else {
            asm volatile("cp.async.wait_group 0;" ::: "memory");
        }
        __syncthreads();

        const __nv_bfloat16* stg = (const __nv_bfloat16*)(sm + s * STAGEB);
        const __nv_bfloat16* sAh = stg;
        const __nv_bfloat16* sAl = stg + 128 * LDSM;
        const __nv_bfloat16* sBh = stg + 2 * 128 * LDSM;
        const __nv_bfloat16* sBl = stg + 3 * 128 * LDSM;

        #pragma unroll
        for (int ks = 0; ks < 2; ks++) {
            FragA ah[4], al[4];
            FragBc bh[4], bl[4];
            #pragma unroll
            for (int i = 0; i < 4; i++) {
                wmma::load_matrix_sync(ah[i], sAh + (wm*64 + i*16) * LDSM + ks*16, LDSM);
                wmma::load_matrix_sync(al[i], sAl + (wm*64 + i*16) * LDSM + ks*16, LDSM);
            }
            #pragma unroll
            for (int j = 0; j < 4; j++) {
                wmma::load_matrix_sync(bh[j], sBh + (wn*64 + j*16) * LDSM + ks*16, LDSM);
                wmma::load_matrix_sync(bl[j], sBl + (wn*64 + j*16) * LDSM + ks*16, LDSM);
            }
            #pragma unroll
            for (int i = 0; i < 4; i++)
                #pragma unroll
                for (int j = 0; j < 4; j++) {
                    wmma::mma_sync(acc[i][j], ah[i], bh[j], acc[i][j]);
                    wmma::mma_sync(acc[i][j], ah[i], bl[j], acc[i][j]);
                    wmma::mma_sync(acc[i][j], al[i], bh[j], acc[i][j]);
                }
        }
        __syncthreads();
    }

    if (mode == 1) {
        #pragma unroll
        for (int i = 0; i < 4; i++) {
            const int m = m0 + wm*64 + i*16;
            #pragma unroll
            for (int j = 0; j < 4; j++) {
                const int n = n0 + wn*64 + j*16;
                wmma::store_matrix_sync(outF + (size_t)m * 1024 + n, acc[i][j],
                                        1024, wmma::mem_row_major);
            }
        }
        return;
    }

    float* sEpi = (float*)sm;
    #pragma unroll
    for (int i = 0; i < 4; i++)
        #pragma unroll
        for (int j = 0; j < 4; j++)
            wmma::store_matrix_sync(sEpi + (wm*64 + i*16) * EPLD + wn*64 + j*16,
                                    acc[i][j], EPLD, wmma::mem_row_major);
    __syncthreads();

    #pragma unroll
    for (int u = 0; u < 64; u++) {
        int e2 = u * 128 + tid;
        int r = e2 >> 6;
        int c = (e2 & 63) * 2;
        float v0 = sEpi[r * EPLD + c];
        float v1 = sEpi[r * EPLD + c + 1];
        float r0, r1;
        uint32_t hv = pack2(v0, v1, &r0, &r1);
        uint32_t lv = pack2lo(r0, r1);
        const int m = m0 + r, n = n0 + c;
        const int b = m >> 10, srow = m & 1023;
        const int h = n >> 6,  d = n & 63;
        size_t addr = ((((size_t)(b*16 + h)) * 1024 + srow) * 64 + d);
        *(uint32_t*)(outHi + addr) = hv;
        *(uint32_t*)(outLo + addr) = lv;
    }
}

// ---------------- fp16x2 2-pass GEMM (Q/K projections, mode-0 epilogue) -----
__device__ __forceinline__ void issue_stage_h(
    const __half* __restrict__ Ah, const __half* __restrict__ Al,
    const __half* __restrict__ Bh,
    uint32_t sbase, int stage, int m0, int n0, int k0, int tid)
{
    #pragma unroll
    for (int u = 0; u < 12; u++) {
        int chunk = u * 128 + tid;         // 1536 chunks of 16B
        int mat = chunk >> 9;
        int r   = (chunk >> 2) & 127;
        int c   = chunk & 3;
        const __half* g;
        if      (mat == 0) g = Ah + (size_t)(m0 + r) * 1024 + k0 + c * 8;
        else if (mat == 1) g = Al + (size_t)(m0 + r) * 1024 + k0 + c * 8;
        else               g = Bh + (size_t)(n0 + r) * 1024 + k0 + c * 8;
        uint32_t dst = sbase + (uint32_t)(stage * STAGEBH + mat * MATB + r * (LDSM*2) + c * 16);
        cp16(dst, g);
    }
    asm volatile("cp.async.commit_group;" ::: "memory");
}

__global__ __launch_bounds__(128, 2) void mma_gemm_h2(
    const __half* __restrict__ Ah, const __half* __restrict__ Al,
    const __half* __restrict__ Bh,
    const float* __restrict__ bias,
    __nv_bfloat16* __restrict__ outHi, __nv_bfloat16* __restrict__ outLo)
{
    extern __shared__ char sm[];
    float* sBias = (float*)(sm + 2 * STAGEBH);
    const uint32_t sbase = smem_u32(sm);
    const int tid = threadIdx.x;
    const int wid = tid >> 5;
    const int m0 = blockIdx.y * 128;
    const int n0 = blockIdx.x * 128;
    const int wm = wid >> 1;
    const int wn = wid & 1;

    for (int idx = tid; idx < 16 * 128; idx += 128)
        sBias[idx] = bias[n0 + (idx & 127)];
    __syncthreads();

    FragC acc[4][4];
    #pragma unroll
    for (int i = 0; i < 4; i++)
        #pragma unroll
        for (int j = 0; j < 4; j++)
            wmma::load_matrix_sync(acc[i][j], sBias + wn*64 + j*16, 128, wmma::mem_row_major);

    issue_stage_h(Ah, Al, Bh, sbase, 0, m0, n0, 0, tid);

    for (int kc = 0; kc < 32; kc++) {
        const int s = kc & 1;
        if (kc + 1 < 32) {
            issue_stage_h(Ah, Al, Bh, sbase, s ^ 1, m0, n0, (kc + 1) * 32, tid);
            asm volatile("cp.async.wait_group 1;" ::: "memory");
        } else {
            asm volatile("cp.async.wait_group 0;" ::: "memory");
        }
        __syncthreads();

        const __half* stg = (const __half*)(sm + s * STAGEBH);
        const __half* sAh = stg;
        const __half* sAl = stg + 128 * LDSM;
        const __half* sBh = stg + 2 * 128 * LDSM;

        #pragma unroll
        for (int ks = 0; ks < 2; ks++) {
            HFragA ah[4], al[4];
            HFragB bh[4];
            #pragma unroll
            for (int i = 0; i < 4; i++) {
                wmma::load_matrix_sync(ah[i], sAh + (wm*64 + i*16) * LDSM + ks*16, LDSM);
                wmma::load_matrix_sync(al[i], sAl + (wm*64 + i*16) * LDSM + ks*16, LDSM);
            }
            #pragma unroll
            for (int j = 0; j < 4; j++)
                wmma::load_matrix_sync(bh[j], sBh + (wn*64 + j*16) * LDSM + ks*16, LDSM);
            #pragma unroll
            for (int i = 0; i < 4; i++)
                #pragma unroll
                for (int j = 0; j < 4; j++) {
                    wmma::mma_sync(acc[i][j], ah[i], bh[j], acc[i][j]);
                    wmma::mma_sync(acc[i][j], al[i], bh[j], acc[i][j]);
                }
        }
        __syncthreads();
    }

    // epilogue: smem roundtrip, split to bf16 hi/lo at [b,h,s,d]
    float* sEpi = (float*)sm;
    #pragma unroll
    for (int i = 0; i < 4; i++)
        #pragma unroll
        for (int j = 0; j < 4; j++)
            wmma::store_matrix_sync(sEpi + (wm*64 + i*16) * EPLD + wn*64 + j*16,
                                    acc[i][j], EPLD, wmma::mem_row_major);
    __syncthreads();

    #pragma unroll
    for (int u = 0; u < 64; u++) {
        int e2 = u * 128 + tid;
        int r = e2 >> 6;
        int c = (e2 & 63) * 2;
        float v0 = sEpi[r * EPLD + c];
        float v1 = sEpi[r * EPLD + c + 1];
        float r0, r1;
        uint32_t hv = pack2(v0, v1, &r0, &r1);
        uint32_t lv = pack2lo(r0, r1);
        const int m = m0 + r, n = n0 + c;
        const int b = m >> 10, srow = m & 1023;
        const int h = n >> 6,  d = n & 63;
        size_t addr = ((((size_t)(b*16 + h)) * 1024 + srow) * 64 + d);
        *(uint32_t*)(outHi + addr) = hv;
        *(uint32_t*)(outLo + addr) = lv;
    }
}

// ---------------- tensor-core flash attention v3 (QK 2-pass) ----------------
#define ALD 72
#define SLD 68
#define TQB 9216
#define oQ   0
#define oKV  36864
#define oP   110592
#define oS   147456
#define ATTN_SMEM 182272

__global__ __launch_bounds__(256) void attn_mma(
    const int* __restrict__ pad,
    __nv_bfloat16* __restrict__ Xhi, __nv_bfloat16* __restrict__ Xlo)
{
    extern __shared__ char sm[];
    const uint32_t sbase = smem_u32(sm);
    const int tid  = threadIdx.x;
    const int w    = tid >> 5, lane = tid & 31;
    const int g    = w >> 2,   wr   = w & 3;
    const int bx   = blockIdx.x;
    const int bh   = blockIdx.y;
    const int b    = bh >> 4, h = bh & 15;
    const int padb = pad[b];
    const int tlim = S_ - padb;
    const int qt   = bx * 2 + g;
    const int q0   = qt * 64;
    const size_t hoff = (size_t)bh * S_ * D_;

    float* sSg = (float*)(sm + oS + g * 17408);
    __nv_bfloat16* sPhg = (__nv_bfloat16*)(sm + oP + g * 18432);
    __nv_bfloat16* sPlg = (__nv_bfloat16*)(sm + oP + g * 18432 + TQB);
    const __nv_bfloat16* sQh = (const __nv_bfloat16*)(sm + oQ + g * 2 * TQB);

    // preload: Q hi tiles (both groups) + K/V tile 0 into stage 0
    #pragma unroll
    for (int u = 0; u < 4; u++) {
        int c = u * 256 + tid;            // 1024 chunks (2 groups x 512)
        int gm = c >> 9;                  // group
        int rc = c & 511;
        int r = rc >> 3, cc = rc & 7;
        const __nv_bfloat16* src = g_Qhi
            + hoff + (size_t)((bx*2 + gm) * 64 + r) * 64 + cc * 8;
        cp16(sbase + oQ + (uint32_t)(gm * 2 * TQB + r * 144 + cc * 16), src);
    }
    #pragma unroll
    for (int u = 0; u < 8; u++) {
        int c = u * 256 + tid;
        int mat = c >> 9;                 // Khi,Klo,Vhi,Vlo
        int rc = c & 511;
        int r = rc >> 3, cc = rc & 7;
        const __nv_bfloat16* src =
            (mat == 0 ? g_Khi : mat == 1 ? g_Klo : mat == 2 ? g_Vhi : g_Vlo)
            + hoff + (size_t)r * 64 + cc * 8;
        cp16(sbase + oKV + (uint32_t)(mat * TQB + r * 144 + cc * 16), src);
    }
    asm volatile("cp.async.commit_group;" ::: "memory");

    const int jtLast = (padb == 0) ? 15 : min(bx * 2 + 1, (tlim - 1) >> 6);

    const int lr = lane >> 1, half = lane & 1;
    const int srow = q0 + wr * 16 + lr;

    float o[32];
    #pragma unroll
    for (int c = 0; c < 32; c++) o[c] = 0.f;
    float mrow = -INFINITY, lrow = 0.f;

    for (int jt = 0; jt <= jtLast; jt++) {
        const int s = jt & 1;
        const int t0 = jt * 64;
        if (jt < jtLast) {
            const int tn = (jt + 1) * 64;
            #pragma unroll
            for (int u = 0; u < 8; u++) {
                int c = u * 256 + tid;
                int mat = c >> 9;
                int rc = c & 511;
                int r = rc >> 3, cc = rc & 7;
                const __nv_bfloat16* src =
                    (mat == 0 ? g_Khi : mat == 1 ? g_Klo : mat == 2 ? g_Vhi : g_Vlo)
                    + hoff + (size_t)(tn + r) * 64 + cc * 8;
                cp16(sbase + oKV + (uint32_t)((s ^ 1) * 36864 + mat * TQB + r * 144 + cc * 16), src);
            }
            asm volatile("cp.async.commit_group;" ::: "memory");
            asm volatile("cp.async.wait_group 1;" ::: "memory");
        } else {
            asm volatile("cp.async.wait_group 0;" ::: "memory");
        }
        __syncthreads();

        const bool act = (padb == 0) || (jt <= qt && t0 < tlim);
        if (act) {
            const __nv_bfloat16* sKh = (const __nv_bfloat16*)(sm + oKV + s * 36864);
            const __nv_bfloat16* sKl = sKh + 64 * ALD;
            const __nv_bfloat16* sVh = sKh + 2 * 64 * ALD;
            const __nv_bfloat16* sVl = sKh + 3 * 64 * ALD;

            // ---- S = Q K^T (2-pass: Qh*Kh + Qh*Kl) ----
            {
                FragA qh[4];
                #pragma unroll
                for (int ks = 0; ks < 4; ks++)
                    wmma::load_matrix_sync(qh[ks], sQh + (wr*16) * ALD + ks*16, ALD);
                FragC acc[4];
                #pragma unroll
                for (int j = 0; j < 4; j++) wmma::fill_fragment(acc[j], 0.f);
                #pragma unroll
                for (int j = 0; j < 4; j++) {
                    #pragma unroll
                    for (int ks = 0; ks < 4; ks++) {
                        FragBc kh, kl;
                        wmma::load_matrix_sync(kh, sKh + (j*16) * ALD + ks*16, ALD);
                        wmma::load_matrix_sync(kl, sKl + (j*16) * ALD + ks*16, ALD);
                        wmma::mma_sync(acc[j], qh[ks], kh, acc[j]);
                        wmma::mma_sync(acc[j], qh[ks], kl, acc[j]);
                    }
                }
                #pragma unroll
                for (int j = 0; j < 4; j++)
                    wmma::store_matrix_sync(sSg + (wr*16) * SLD + j*16, acc[j],
                                            SLD, wmma::mem_row_major);
            }
            __syncwarp();

            // ---- softmax (regs, vectorized) ----
            float alpha;
            {
                const float4* Srow4 = (const float4*)(sSg + (wr*16 + lr) * SLD + half * 32);
                const int tbase = t0 + half * 32;
                float v[32];
                #pragma unroll
                for (int q4 = 0; q4 < 8; q4++) {
                    float4 f = Srow4[q4];
                    v[q4*4+0] = f.x; v[q4*4+1] = f.y; v[q4*4+2] = f.z; v[q4*4+3] = f.w;
                }
                float mloc = -INFINITY;
                #pragma unroll
                for (int c = 0; c < 32; c++) {
                    const int t = tbase + c;
                    float val = v[c] * 0.03125f;
                    if ((t > srow) | (t >= tlim) | (padb == 0)) val -= 1e9f;
                    v[c] = val;
                    mloc = fmaxf(mloc, val);
                }
                mloc = fmaxf(mloc, __shfl_xor_sync(0xffffffffu, mloc, 1));
                const float mnew = fmaxf(mrow, mloc);
                alpha = __expf(mrow - mnew);
                uint32_t* Pr32 = (uint32_t*)(sPhg + (wr*16 + lr) * ALD + half * 32);
                uint32_t* Pl32 = (uint32_t*)(sPlg + (wr*16 + lr) * ALD + half * 32);
                float lsum = 0.f;
                #pragma unroll
                for (int c = 0; c < 32; c += 2) {
                    float p0 = __expf(v[c]   - mnew);
                    float p1 = __expf(v[c+1] - mnew);
                    lsum += p0; lsum += p1;
                    float r0, r1;
                    Pr32[c >> 1] = pack2(p0, p1, &r0, &r1);
                    Pl32[c >> 1] = pack2lo(r0, r1);
                }
                lsum += __shfl_xor_sync(0xffffffffu, lsum, 1);
                lrow = lrow * alpha + lsum;
                mrow = mnew;
            }
            __syncwarp();

            // ---- PV (bf16x3), result overwrites S rows (warp-local) ----
            {
                FragA pfh[4], pfl[4];
                #pragma unroll
                for (int ks = 0; ks < 4; ks++) {
                    wmma::load_matrix_sync(pfh[ks], sPhg + (wr*16) * ALD + ks*16, ALD);
                    wmma::load_matrix_sync(pfl[ks], sPlg + (wr*16) * ALD + ks*16, ALD);
                }
                FragC oa[4];
                #pragma unroll
                for (int n = 0; n < 4; n++) wmma::fill_fragment(oa[n], 0.f);
                #pragma unroll
                for (int n = 0; n < 4; n++) {
                    #pragma unroll
                    for (int ks = 0; ks < 4; ks++) {
                        FragBr vh, vl;
                        wmma::load_matrix_sync(vh, sVh + (ks*16) * ALD + n*16, ALD);
                        wmma::load_matrix_sync(vl, sVl + (ks*16) * ALD + n*16, ALD);
                        wmma::mma_sync(oa[n], pfh[ks], vh, oa[n]);
                        wmma::mma_sync(oa[n], pfh[ks], vl, oa[n]);
                        wmma::mma_sync(oa[n], pfl[ks], vh, oa[n]);
                    }
                }
                #pragma unroll
                for (int n = 0; n < 4; n++)
                    wmma::store_matrix_sync(sSg + (wr*16) * SLD + n*16, oa[n],
                                            SLD, wmma::mem_row_major);
            }
            __syncwarp();

            // ---- O = O*alpha + PV (registers) ----
            {
                const float4* Pv4 = (const float4*)(sSg + (wr*16 + lr) * SLD + half * 32);
                #pragma unroll
                for (int q4 = 0; q4 < 8; q4++) {
                    float4 f = Pv4[q4];
                    o[q4*4+0] = o[q4*4+0] * alpha + f.x;
                    o[q4*4+1] = o[q4*4+1] * alpha + f.y;
                    o[q4*4+2] = o[q4*4+2] * alpha + f.z;
                    o[q4*4+3] = o[q4*4+3] * alpha + f.w;
                }
            }
        }
        __syncthreads();
    }

    // epilogue: normalize, split, store (from registers)
    {
        const float inv = 1.f / lrow;
        const size_t base = ((size_t)(b * S_ + srow)) * DM_ + h * 64 + half * 32;
        #pragma unroll
        for (int c = 0; c < 32; c += 2) {
            float v0 = o[c] * inv, v1 = o[c+1] * inv;
            float r0, r1;
            uint32_t hv = pack2(v0, v1, &r0, &r1);
            uint32_t lv = pack2lo(r0, r1);
            *(uint32_t*)(Xhi + base + c) = hv;
            *(uint32_t*)(Xlo + base + c) = lv;
        }
    }
}

// ---------------------------------------------------------------------------
extern "C" void kernel_launch(void* const* d_in, const int* in_sizes, int n_in,
                              void* d_out, int out_size)
{
    const float* Q   = (const float*)d_in[0];
    const float* K   = (const float*)d_in[1];
    const float* V   = (const float*)d_in[2];
    const int*   pad = (const int*)  d_in[3];
    const float* Wq  = (const float*)d_in[4];
    const float* bq  = (const float*)d_in[5];
    const float* Wk  = (const float*)d_in[6];
    const float* bk  = (const float*)d_in[7];
    const float* Wv  = (const float*)d_in[8];
    const float* bv  = (const float*)d_in[9];
    const float* Wo  = (const float*)d_in[10];
    const float* bo  = (const float*)d_in[11];
    float* out = (float*)d_out;

    __nv_bfloat16 *qhi, *qlo, *khi, *klo, *vhi, *vlo, *ahi, *alo, *whi, *wlo;
    cudaGetSymbolAddress((void**)&qhi, g_Qhi);
    cudaGetSymbolAddress((void**)&qlo, g_Qlo);
    cudaGetSymbolAddress((void**)&khi, g_Khi);
    cudaGetSymbolAddress((void**)&klo, g_Klo);
    cudaGetSymbolAddress((void**)&vhi, g_Vhi);
    cudaGetSymbolAddress((void**)&vlo, g_Vlo);
    cudaGetSymbolAddress((void**)&ahi, g_Ahi);
    cudaGetSymbolAddress((void**)&alo, g_Alo);
    cudaGetSymbolAddress((void**)&whi, g_Whi);
    cudaGetSymbolAddress((void**)&wlo, g_Wlo);

    cudaFuncSetAttribute(mma_gemm,
                         cudaFuncAttributeMaxDynamicSharedMemorySize, GSMEM);
    cudaFuncSetAttribute(mma_gemm_h2,
                         cudaFuncAttributeMaxDynamicSharedMemorySize, GSMEMH);
    cudaFuncSetAttribute(attn_mma,
                         cudaFuncAttributeMaxDynamicSharedMemorySize, ATTN_SMEM);

    const int n4 = (B_*S_*DM_) / 4;
    const dim3 gw(32, 32), bw(32, 8);
    const dim3 gg(8, 64);

    // Q projection (fp16x2, 2-pass)
    split_wT_h<<<gw, bw>>>(Wq, (__half*)whi);
    split_act_h<<<n4/256, 256>>>((const float4*)Q, (uint2*)ahi, (uint2*)alo, n4);
    mma_gemm_h2<<<gg, 128, GSMEMH>>>((const __half*)ahi, (const __half*)alo,
                                     (const __half*)whi, bq, qhi, qlo);
    // K projection (fp16x2, 2-pass)
    split_wT_h<<<gw, bw>>>(Wk, (__half*)whi);
    split_act_h<<<n4/256, 256>>>((const float4*)K, (uint2*)ahi, (uint2*)alo, n4);
    mma_gemm_h2<<<gg, 128, GSMEMH>>>((const __half*)ahi, (const __half*)alo,
                                     (const __half*)whi, bk, khi, klo);
    // V projection (bf16x3, 3-pass)
    split_wT<<<gw, bw>>>(Wv, whi, wlo, 0);
    split_act<<<n4/256, 256>>>((const float4*)V, (uint2*)ahi, (uint2*)alo, n4);
    mma_gemm<<<gg, 128, GSMEM>>>(ahi, alo, whi, wlo, bv, nullptr, vhi, vlo, 0);

    // attention -> X hi/lo into ahi/alo
    attn_mma<<<dim3(8, 128), 256, ATTN_SMEM>>>(pad, ahi, alo);

    // output projection (bf16x3, fp32 out)
    split_wT<<<gw, bw>>>(Wo, whi, wlo, 1);
    mma_gemm<<<gg, 128, GSMEM>>>(ahi, alo, whi, wlo, bo, out, nullptr, nullptr, 1);
}

// round 10
// speedup vs baseline: 1.7362x; 1.1966x over previous
#include <cuda_runtime.h>
#include <cuda_bf16.h>
#include <cuda_fp16.h>
#include <mma.h>
#include <math.h>
#include <stdint.h>

using namespace nvcuda;

#define S_   1024
#define DM_  1024
#define B_   8
#define H_   16
#define D_   64

// ---------------- scratch (__device__ globals; no allocation) ----------------
__device__ __nv_bfloat16 g_Qhi[B_*H_*S_*D_];  // [b,h,s,d] (fp16 payload for Q)
__device__ __nv_bfloat16 g_Khi[B_*H_*S_*D_];  // [b,h,s,d] (fp16 payload for K)
__device__ __nv_bfloat16 g_Vhi[B_*H_*S_*D_];  // bf16 hi
__device__ __nv_bfloat16 g_Vlo[B_*H_*S_*D_];  // bf16 lo
__device__ __nv_bfloat16 g_Ahi[B_*S_*DM_];    // activation hi/lo (inputs, then X)
__device__ __nv_bfloat16 g_Alo[B_*S_*DM_];
__device__ __nv_bfloat16 g_Whi[DM_*DM_];      // weight-transposed hi/lo [N][K]
__device__ __nv_bfloat16 g_Wlo[DM_*DM_];

// ---------------- helpers ----------------
__device__ __forceinline__ uint32_t smem_u32(const void* p) {
    uint32_t a;
    asm("{ .reg .u64 t; cvta.to.shared.u64 t, %1; cvt.u32.u64 %0, t; }"
        : "=r"(a) : "l"(p));
    return a;
}
__device__ __forceinline__ void cp16(uint32_t dst, const void* src) {
    asm volatile("cp.async.cg.shared.global [%0], [%1], 16;" :: "r"(dst), "l"(src));
}
__device__ __forceinline__ uint32_t pack2(float a, float b, float* ra, float* rb) {
    __nv_bfloat16 ha = __float2bfloat16(a), hb = __float2bfloat16(b);
    *ra = a - __bfloat162float(ha);
    *rb = b - __bfloat162float(hb);
    return (uint32_t)__bfloat16_as_ushort(ha) |
           ((uint32_t)__bfloat16_as_ushort(hb) << 16);
}
__device__ __forceinline__ uint32_t pack2lo(float a, float b) {
    __nv_bfloat16 ha = __float2bfloat16(a), hb = __float2bfloat16(b);
    return (uint32_t)__bfloat16_as_ushort(ha) |
           ((uint32_t)__bfloat16_as_ushort(hb) << 16);
}
__device__ __forceinline__ uint32_t pack2h(float a, float b) {
    __half ha = __float2half_rn(a), hb = __float2half_rn(b);
    return (uint32_t)__half_as_ushort(ha) |
           ((uint32_t)__half_as_ushort(hb) << 16);
}

// ---------------- conversion kernels ----------------
__global__ __launch_bounds__(256) void split_act(
    const float4* __restrict__ src, uint2* __restrict__ hi, uint2* __restrict__ lo, int n4)
{
    int i = blockIdx.x * 256 + threadIdx.x;
    if (i >= n4) return;
    float4 v = src[i];
    float rx, ry, rz, rw;
    uint2 h, l;
    h.x = pack2(v.x, v.y, &rx, &ry);
    h.y = pack2(v.z, v.w, &rz, &rw);
    l.x = pack2lo(rx, ry);
    l.y = pack2lo(rz, rw);
    hi[i] = h; lo[i] = l;
}

// fp16 single (Q/K inputs)
__global__ __launch_bounds__(256) void cvt_act_h(
    const float4* __restrict__ src, uint2* __restrict__ hi, int n4)
{
    int i = blockIdx.x * 256 + threadIdx.x;
    if (i >= n4) return;
    float4 v = src[i];
    uint2 h;
    h.x = pack2h(v.x, v.y);
    h.y = pack2h(v.z, v.w);
    hi[i] = h;
}

// weight transpose+split bf16: out[n][k]; mode0 src=W[h][k][d], mode1 src=Wo[k][n]
__global__ __launch_bounds__(256) void split_wT(
    const float* __restrict__ W, __nv_bfloat16* __restrict__ hi,
    __nv_bfloat16* __restrict__ lo, int mode)
{
    __shared__ float t[32][33];
    int k0 = blockIdx.x * 32, n0 = blockIdx.y * 32;
    int tx = threadIdx.x, ty = threadIdx.y;   // 32 x 8
    #pragma unroll
    for (int i = 0; i < 4; i++) {
        int k = k0 + ty + 8*i, n = n0 + tx;
        float v = mode ? W[(size_t)k * 1024 + n]
                       : W[(((size_t)(n >> 6)) * 1024 + k) * 64 + (n & 63)];
        t[ty + 8*i][tx] = v;
    }
    __syncthreads();
    #pragma unroll
    for (int i = 0; i < 4; i++) {
        int n = n0 + ty + 8*i, k = k0 + tx;
        float v = t[tx][ty + 8*i];
        __nv_bfloat16 h = __float2bfloat16(v);
        __nv_bfloat16 l = __float2bfloat16(v - __bfloat162float(h));
        hi[(size_t)n * 1024 + k] = h;
        lo[(size_t)n * 1024 + k] = l;
    }
}

// weight transpose, fp16 hi only: src=W[h][k][d]
__global__ __launch_bounds__(256) void split_wT_h(
    const float* __restrict__ W, __half* __restrict__ hi)
{
    __shared__ float t[32][33];
    int k0 = blockIdx.x * 32, n0 = blockIdx.y * 32;
    int tx = threadIdx.x, ty = threadIdx.y;
    #pragma unroll
    for (int i = 0; i < 4; i++) {
        int k = k0 + ty + 8*i, n = n0 + tx;
        t[ty + 8*i][tx] = W[(((size_t)(n >> 6)) * 1024 + k) * 64 + (n & 63)];
    }
    __syncthreads();
    #pragma unroll
    for (int i = 0; i < 4; i++) {
        int n = n0 + ty + 8*i, k = k0 + tx;
        hi[(size_t)n * 1024 + k] = __float2half_rn(t[tx][ty + 8*i]);
    }
}

// ---------------- fragment typedefs / sizes ----------------
#define LDSM   40
#define MATB   (128 * LDSM * 2)
#define STAGEB (4 * MATB)
#define GSMEM  (2 * STAGEB + 16 * 128 * 4)
#define STAGEB1 (2 * MATB)
#define EPLD   132
// NOTE: the smem-roundtrip epilogue needs 128*EPLD*4 = 67584 bytes; GSMEM1 must
// cover max(mainloop = 2*STAGEB1 + bias = 49152, epilogue = 67584).
#define GSMEM1 (128 * EPLD * 4)

typedef wmma::fragment<wmma::matrix_a, 16,16,16, __nv_bfloat16, wmma::row_major> FragA;
typedef wmma::fragment<wmma::matrix_b, 16,16,16, __nv_bfloat16, wmma::col_major> FragBc;
typedef wmma::fragment<wmma::matrix_b, 16,16,16, __nv_bfloat16, wmma::row_major> FragBr;
typedef wmma::fragment<wmma::matrix_a, 16,16,16, __half, wmma::row_major> HFragA;
typedef wmma::fragment<wmma::matrix_b, 16,16,16, __half, wmma::col_major> HFragB;
typedef wmma::fragment<wmma::accumulator, 16,16,16, float> FragC;

// ---------------- bf16x3 GEMM (V proj + out proj) ----------------
__device__ __forceinline__ void issue_stage(
    const __nv_bfloat16* __restrict__ Ahi, const __nv_bfloat16* __restrict__ Alo,
    const __nv_bfloat16* __restrict__ Bhi, const __nv_bfloat16* __restrict__ Blo,
    uint32_t sbase, int stage, int m0, int n0, int k0, int tid)
{
    #pragma unroll
    for (int u = 0; u < 16; u++) {
        int chunk = u * 128 + tid;
        int mat = chunk >> 9;
        int r   = (chunk >> 2) & 127;
        int c   = chunk & 3;
        const __nv_bfloat16* g;
        if      (mat == 0) g = Ahi + (size_t)(m0 + r) * 1024 + k0 + c * 8;
        else if (mat == 1) g = Alo + (size_t)(m0 + r) * 1024 + k0 + c * 8;
        else if (mat == 2) g = Bhi + (size_t)(n0 + r) * 1024 + k0 + c * 8;
        else               g = Blo + (size_t)(n0 + r) * 1024 + k0 + c * 8;
        uint32_t dst = sbase + (uint32_t)(stage * STAGEB + mat * MATB + r * (LDSM*2) + c * 16);
        cp16(dst, g);
    }
    asm volatile("cp.async.commit_group;" ::: "memory");
}

__global__ __launch_bounds__(128, 2) void mma_gemm(
    const __nv_bfloat16* __restrict__ Ahi, const __nv_bfloat16* __restrict__ Alo,
    const __nv_bfloat16* __restrict__ Bhi, const __nv_bfloat16* __restrict__ Blo,
    const float* __restrict__ bias, float* __restrict__ outF,
    __nv_bfloat16* __restrict__ outHi, __nv_bfloat16* __restrict__ outLo, int mode)
{
    extern __shared__ char sm[];
    float* sBias = (float*)(sm + 2 * STAGEB);
    const uint32_t sbase = smem_u32(sm);
    const int tid = threadIdx.x;
    const int wid = tid >> 5;
    const int m0 = blockIdx.y * 128;
    const int n0 = blockIdx.x * 128;
    const int wm = wid >> 1;
    const int wn = wid & 1;

    for (int idx = tid; idx < 16 * 128; idx += 128)
        sBias[idx] = bias[n0 + (idx & 127)];
    __syncthreads();

    FragC acc[4][4];
    #pragma unroll
    for (int i = 0; i < 4; i++)
        #pragma unroll
        for (int j = 0; j < 4; j++)
            wmma::load_matrix_sync(acc[i][j], sBias + wn*64 + j*16, 128, wmma::mem_row_major);

    issue_stage(Ahi, Alo, Bhi, Blo, sbase, 0, m0, n0, 0, tid);

    for (int kc = 0; kc < 32; kc++) {
        const int s = kc & 1;
        if (kc + 1 < 32) {
            issue_stage(Ahi, Alo, Bhi, Blo, sbase, s ^ 1, m0, n0, (kc + 1) * 32, tid);
            asm volatile("cp.async.wait_group 1;" ::: "memory");
        } else {
            asm volatile("cp.async.wait_group 0;" ::: "memory");
        }
        __syncthreads();

        const __nv_bfloat16* stg = (const __nv_bfloat16*)(sm + s * STAGEB);
        const __nv_bfloat16* sAh = stg;
        const __nv_bfloat16* sAl = stg + 128 * LDSM;
        const __nv_bfloat16* sBh = stg + 2 * 128 * LDSM;
        const __nv_bfloat16* sBl = stg + 3 * 128 * LDSM;

        #pragma unroll
        for (int ks = 0; ks < 2; ks++) {
            FragA ah[4], al[4];
            FragBc bh[4], bl[4];
            #pragma unroll
            for (int i = 0; i < 4; i++) {
                wmma::load_matrix_sync(ah[i], sAh + (wm*64 + i*16) * LDSM + ks*16, LDSM);
                wmma::load_matrix_sync(al[i], sAl + (wm*64 + i*16) * LDSM + ks*16, LDSM);
            }
            #pragma unroll
            for (int j = 0; j < 4; j++) {
                wmma::load_matrix_sync(bh[j], sBh + (wn*64 + j*16) * LDSM + ks*16, LDSM);
                wmma::load_matrix_sync(bl[j], sBl + (wn*64 + j*16) * LDSM + ks*16, LDSM);
            }
            #pragma unroll
            for (int i = 0; i < 4; i++)
                #pragma unroll
                for (int j = 0; j < 4; j++) {
                    wmma::mma_sync(acc[i][j], ah[i], bh[j], acc[i][j]);
                    wmma::mma_sync(acc[i][j], ah[i], bl[j], acc[i][j]);
                    wmma::mma_sync(acc[i][j], al[i], bh[j], acc[i][j]);
                }
        }
        __syncthreads();
    }

    if (mode == 1) {
        #pragma unroll
        for (int i = 0; i < 4; i++) {
            const int m = m0 + wm*64 + i*16;
            #pragma unroll
            for (int j = 0; j < 4; j++) {
                const int n = n0 + wn*64 + j*16;
                wmma::store_matrix_sync(outF + (size_t)m * 1024 + n, acc[i][j],
                                        1024, wmma::mem_row_major);
            }
        }
        return;
    }

    float* sEpi = (float*)sm;
    #pragma unroll
    for (int i = 0; i < 4; i++)
        #pragma unroll
        for (int j = 0; j < 4; j++)
            wmma::store_matrix_sync(sEpi + (wm*64 + i*16) * EPLD + wn*64 + j*16,
                                    acc[i][j], EPLD, wmma::mem_row_major);
    __syncthreads();

    #pragma unroll
    for (int u = 0; u < 64; u++) {
        int e2 = u * 128 + tid;
        int r = e2 >> 6;
        int c = (e2 & 63) * 2;
        float v0 = sEpi[r * EPLD + c];
        float v1 = sEpi[r * EPLD + c + 1];
        float r0, r1;
        uint32_t hv = pack2(v0, v1, &r0, &r1);
        uint32_t lv = pack2lo(r0, r1);
        const int m = m0 + r, n = n0 + c;
        const int b = m >> 10, srow = m & 1023;
        const int h = n >> 6,  d = n & 63;
        size_t addr = ((((size_t)(b*16 + h)) * 1024 + srow) * 64 + d);
        *(uint32_t*)(outHi + addr) = hv;
        *(uint32_t*)(outLo + addr) = lv;
    }
}

// ---------------- fp16 single-pass GEMM (Q/K projections) -------------------
__device__ __forceinline__ void issue_stage_h1(
    const __half* __restrict__ Ah, const __half* __restrict__ Bh,
    uint32_t sbase, int stage, int m0, int n0, int k0, int tid)
{
    #pragma unroll
    for (int u = 0; u < 8; u++) {
        int chunk = u * 128 + tid;         // 1024 chunks of 16B
        int mat = chunk >> 9;
        int r   = (chunk >> 2) & 127;
        int c   = chunk & 3;
        const __half* g = (mat == 0)
            ? Ah + (size_t)(m0 + r) * 1024 + k0 + c * 8
            : Bh + (size_t)(n0 + r) * 1024 + k0 + c * 8;
        uint32_t dst = sbase + (uint32_t)(stage * STAGEB1 + mat * MATB + r * (LDSM*2) + c * 16);
        cp16(dst, g);
    }
    asm volatile("cp.async.commit_group;" ::: "memory");
}

__global__ __launch_bounds__(128, 2) void mma_gemm_h1(
    const __half* __restrict__ Ah, const __half* __restrict__ Bh,
    const float* __restrict__ bias, __half* __restrict__ outH)
{
    extern __shared__ char sm[];
    float* sBias = (float*)(sm + 2 * STAGEB1);
    const uint32_t sbase = smem_u32(sm);
    const int tid = threadIdx.x;
    const int wid = tid >> 5;
    const int m0 = blockIdx.y * 128;
    const int n0 = blockIdx.x * 128;
    const int wm = wid >> 1;
    const int wn = wid & 1;

    for (int idx = tid; idx < 16 * 128; idx += 128)
        sBias[idx] = bias[n0 + (idx & 127)];
    __syncthreads();

    FragC acc[4][4];
    #pragma unroll
    for (int i = 0; i < 4; i++)
        #pragma unroll
        for (int j = 0; j < 4; j++)
            wmma::load_matrix_sync(acc[i][j], sBias + wn*64 + j*16, 128, wmma::mem_row_major);

    issue_stage_h1(Ah, Bh, sbase, 0, m0, n0, 0, tid);

    for (int kc = 0; kc < 32; kc++) {
        const int s = kc & 1;
        if (kc + 1 < 32) {
            issue_stage_h1(Ah, Bh, sbase, s ^ 1, m0, n0, (kc + 1) * 32, tid);
            asm volatile("cp.async.wait_group 1;" ::: "memory");
        } else {
            asm volatile("cp.async.wait_group 0;" ::: "memory");
        }
        __syncthreads();

        const __half* stg = (const __half*)(sm + s * STAGEB1);
        const __half* sAh = stg;
        const __half* sBh = stg + 128 * LDSM;

        #pragma unroll
        for (int ks = 0; ks < 2; ks++) {
            HFragA ah[4];
            HFragB bh[4];
            #pragma unroll
            for (int i = 0; i < 4; i++)
                wmma::load_matrix_sync(ah[i], sAh + (wm*64 + i*16) * LDSM + ks*16, LDSM);
            #pragma unroll
            for (int j = 0; j < 4; j++)
                wmma::load_matrix_sync(bh[j], sBh + (wn*64 + j*16) * LDSM + ks*16, LDSM);
            #pragma unroll
            for (int i = 0; i < 4; i++)
                #pragma unroll
                for (int j = 0; j < 4; j++)
                    wmma::mma_sync(acc[i][j], ah[i], bh[j], acc[i][j]);
        }
        __syncthreads();
    }

    // epilogue: smem roundtrip, fp16 out at [b,h,s,d]
    float* sEpi = (float*)sm;
    #pragma unroll
    for (int i = 0; i < 4; i++)
        #pragma unroll
        for (int j = 0; j < 4; j++)
            wmma::store_matrix_sync(sEpi + (wm*64 + i*16) * EPLD + wn*64 + j*16,
                                    acc[i][j], EPLD, wmma::mem_row_major);
    __syncthreads();

    #pragma unroll
    for (int u = 0; u < 64; u++) {
        int e2 = u * 128 + tid;
        int r = e2 >> 6;
        int c = (e2 & 63) * 2;
        float v0 = sEpi[r * EPLD + c];
        float v1 = sEpi[r * EPLD + c + 1];
        uint32_t hv = pack2h(v0, v1);
        const int m = m0 + r, n = n0 + c;
        const int b = m >> 10, srow = m & 1023;
        const int h = n >> 6,  d = n & 63;
        size_t addr = ((((size_t)(b*16 + h)) * 1024 + srow) * 64 + d);
        *(uint32_t*)(outH + addr) = hv;
    }
}

// ---------------- tensor-core flash attention v4 ----------------------------
// Q/K fp16 single-pass QK; PV bf16x3. 2 q-tiles/CTA, double-buffered K/V.
#define ALD 72
#define SLD 68
#define TQB 9216
#define oQ   0                          // 2 tiles (fp16)          18432
#define oKV  18432                      // 2 stages x 3 tiles      55296
#define oP   73728                      // 2 groups x {hi,lo}      36864
#define oS   110592                     // 2 groups fp32 64xSLD    34816
#define ATTN_SMEM 145408
#define KVSTG (3 * TQB)

__global__ __launch_bounds__(256) void attn_mma(
    const int* __restrict__ pad,
    const __half* __restrict__ Qg, const __half* __restrict__ Kg,
    __nv_bfloat16* __restrict__ Xhi, __nv_bfloat16* __restrict__ Xlo)
{
    extern __shared__ char sm[];
    const uint32_t sbase = smem_u32(sm);
    const int tid  = threadIdx.x;
    const int w    = tid >> 5, lane = tid & 31;
    const int g    = w >> 2,   wr   = w & 3;
    const int bx   = blockIdx.x;
    const int bh   = blockIdx.y;
    const int b    = bh >> 4, h = bh & 15;
    const int padb = pad[b];
    const int tlim = S_ - padb;
    const int qt   = bx * 2 + g;
    const int q0   = qt * 64;
    const size_t hoff = (size_t)bh * S_ * D_;

    float* sSg = (float*)(sm + oS + g * 17408);
    __nv_bfloat16* sPhg = (__nv_bfloat16*)(sm + oP + g * 18432);
    __nv_bfloat16* sPlg = (__nv_bfloat16*)(sm + oP + g * 18432 + TQB);
    const __half* sQ = (const __half*)(sm + oQ + g * TQB);

    // preload: Q tiles (fp16, both groups) + K/V tile 0 into stage 0
    #pragma unroll
    for (int u = 0; u < 4; u++) {
        int c = u * 256 + tid;            // 1024 chunks
        int gm = c >> 9;
        int rc = c & 511;
        int r = rc >> 3, cc = rc & 7;
        const __half* src = Qg + hoff + (size_t)((bx*2 + gm) * 64 + r) * 64 + cc * 8;
        cp16(sbase + oQ + (uint32_t)(gm * TQB + r * 144 + cc * 16), src);
    }
    #pragma unroll
    for (int u = 0; u < 6; u++) {
        int c = u * 256 + tid;            // 1536 chunks: K, Vhi, Vlo
        int mat = c >> 9;
        int rc = c & 511;
        int r = rc >> 3, cc = rc & 7;
        const void* src;
        if (mat == 0) src = Kg + hoff + (size_t)r * 64 + cc * 8;
        else if (mat == 1) src = g_Vhi + hoff + (size_t)r * 64 + cc * 8;
        else src = g_Vlo + hoff + (size_t)r * 64 + cc * 8;
        cp16(sbase + oKV + (uint32_t)(mat * TQB + r * 144 + cc * 16), src);
    }
    asm volatile("cp.async.commit_group;" ::: "memory");

    const int jtLast = (padb == 0) ? 15 : min(bx * 2 + 1, (tlim - 1) >> 6);

    const int lr = lane >> 1, half = lane & 1;
    const int srow = q0 + wr * 16 + lr;

    float o[32];
    #pragma unroll
    for (int c = 0; c < 32; c++) o[c] = 0.f;
    float mrow = -INFINITY, lrow = 0.f;

    for (int jt = 0; jt <= jtLast; jt++) {
        const int s = jt & 1;
        const int t0 = jt * 64;
        if (jt < jtLast) {
            const int tn = (jt + 1) * 64;
            #pragma unroll
            for (int u = 0; u < 6; u++) {
                int c = u * 256 + tid;
                int mat = c >> 9;
                int rc = c & 511;
                int r = rc >> 3, cc = rc & 7;
                const void* src;
                if (mat == 0) src = Kg + hoff + (size_t)(tn + r) * 64 + cc * 8;
                else if (mat == 1) src = g_Vhi + hoff + (size_t)(tn + r) * 64 + cc * 8;
                else src = g_Vlo + hoff + (size_t)(tn + r) * 64 + cc * 8;
                cp16(sbase + oKV + (uint32_t)((s ^ 1) * KVSTG + mat * TQB + r * 144 + cc * 16), src);
            }
            asm volatile("cp.async.commit_group;" ::: "memory");
            asm volatile("cp.async.wait_group 1;" ::: "memory");
        } else {
            asm volatile("cp.async.wait_group 0;" ::: "memory");
        }
        __syncthreads();

        const bool act = (padb == 0) || (jt <= qt && t0 < tlim);
        if (act) {
            const __half* sK = (const __half*)(sm + oKV + s * KVSTG);
            const __nv_bfloat16* sVh = (const __nv_bfloat16*)(sm + oKV + s * KVSTG + TQB);
            const __nv_bfloat16* sVl = (const __nv_bfloat16*)(sm + oKV + s * KVSTG + 2 * TQB);

            // ---- S = Q K^T (single-pass fp16) ----
            {
                HFragA qf[4];
                #pragma unroll
                for (int ks = 0; ks < 4; ks++)
                    wmma::load_matrix_sync(qf[ks], sQ + (wr*16) * ALD + ks*16, ALD);
                FragC acc[4];
                #pragma unroll
                for (int j = 0; j < 4; j++) wmma::fill_fragment(acc[j], 0.f);
                #pragma unroll
                for (int j = 0; j < 4; j++) {
                    #pragma unroll
                    for (int ks = 0; ks < 4; ks++) {
                        HFragB kf;
                        wmma::load_matrix_sync(kf, sK + (j*16) * ALD + ks*16, ALD);
                        wmma::mma_sync(acc[j], qf[ks], kf, acc[j]);
                    }
                }
                #pragma unroll
                for (int j = 0; j < 4; j++)
                    wmma::store_matrix_sync(sSg + (wr*16) * SLD + j*16, acc[j],
                                            SLD, wmma::mem_row_major);
            }
            __syncwarp();

            // ---- softmax (regs, vectorized) ----
            float alpha;
            {
                const float4* Srow4 = (const float4*)(sSg + (wr*16 + lr) * SLD + half * 32);
                const int tbase = t0 + half * 32;
                float v[32];
                #pragma unroll
                for (int q4 = 0; q4 < 8; q4++) {
                    float4 f = Srow4[q4];
                    v[q4*4+0] = f.x; v[q4*4+1] = f.y; v[q4*4+2] = f.z; v[q4*4+3] = f.w;
                }
                float mloc = -INFINITY;
                #pragma unroll
                for (int c = 0; c < 32; c++) {
                    const int t = tbase + c;
                    float val = v[c] * 0.03125f;
                    if ((t > srow) | (t >= tlim) | (padb == 0)) val -= 1e9f;
                    v[c] = val;
                    mloc = fmaxf(mloc, val);
                }
                mloc = fmaxf(mloc, __shfl_xor_sync(0xffffffffu, mloc, 1));
                const float mnew = fmaxf(mrow, mloc);
                alpha = __expf(mrow - mnew);
                uint32_t* Pr32 = (uint32_t*)(sPhg + (wr*16 + lr) * ALD + half * 32);
                uint32_t* Pl32 = (uint32_t*)(sPlg + (wr*16 + lr) * ALD + half * 32);
                float lsum = 0.f;
                #pragma unroll
                for (int c = 0; c < 32; c += 2) {
                    float p0 = __expf(v[c]   - mnew);
                    float p1 = __expf(v[c+1] - mnew);
                    lsum += p0; lsum += p1;
                    float r0, r1;
                    Pr32[c >> 1] = pack2(p0, p1, &r0, &r1);
                    Pl32[c >> 1] = pack2lo(r0, r1);
                }
                lsum += __shfl_xor_sync(0xffffffffu, lsum, 1);
                lrow = lrow * alpha + lsum;
                mrow = mnew;
            }
            __syncwarp();

            // ---- PV (bf16x3), result overwrites S rows (warp-local) ----
            {
                FragA pfh[4], pfl[4];
                #pragma unroll
                for (int ks = 0; ks < 4; ks++) {
                    wmma::load_matrix_sync(pfh[ks], sPhg + (wr*16) * ALD + ks*16, ALD);
                    wmma::load_matrix_sync(pfl[ks], sPlg + (wr*16) * ALD + ks*16, ALD);
                }
                FragC oa[4];
                #pragma unroll
                for (int n = 0; n < 4; n++) wmma::fill_fragment(oa[n], 0.f);
                #pragma unroll
                for (int n = 0; n < 4; n++) {
                    #pragma unroll
                    for (int ks = 0; ks < 4; ks++) {
                        FragBr vh, vl;
                        wmma::load_matrix_sync(vh, sVh + (ks*16) * ALD + n*16, ALD);
                        wmma::load_matrix_sync(vl, sVl + (ks*16) * ALD + n*16, ALD);
                        wmma::mma_sync(oa[n], pfh[ks], vh, oa[n]);
                        wmma::mma_sync(oa[n], pfh[ks], vl, oa[n]);
                        wmma::mma_sync(oa[n], pfl[ks], vh, oa[n]);
                    }
                }
                #pragma unroll
                for (int n = 0; n < 4; n++)
                    wmma::store_matrix_sync(sSg + (wr*16) * SLD + n*16, oa[n],
                                            SLD, wmma::mem_row_major);
            }
            __syncwarp();

            // ---- O = O*alpha + PV (registers) ----
            {
                const float4* Pv4 = (const float4*)(sSg + (wr*16 + lr) * SLD + half * 32);
                #pragma unroll
                for (int q4 = 0; q4 < 8; q4++) {
                    float4 f = Pv4[q4];
                    o[q4*4+0] = o[q4*4+0] * alpha + f.x;
                    o[q4*4+1] = o[q4*4+1] * alpha + f.y;
                    o[q4*4+2] = o[q4*4+2] * alpha + f.z;
                    o[q4*4+3] = o[q4*4+3] * alpha + f.w;
                }
            }
        }
        __syncthreads();
    }

    // epilogue: normalize, split, store (from registers)
    {
        const float inv = 1.f / lrow;
        const size_t base = ((size_t)(b * S_ + srow)) * DM_ + h * 64 + half * 32;
        #pragma unroll
        for (int c = 0; c < 32; c += 2) {
            float v0 = o[c] * inv, v1 = o[c+1] * inv;
            float r0, r1;
            uint32_t hv = pack2(v0, v1, &r0, &r1);
            uint32_t lv = pack2lo(r0, r1);
            *(uint32_t*)(Xhi + base + c) = hv;
            *(uint32_t*)(Xlo + base + c) = lv;
        }
    }
}

// ---------------------------------------------------------------------------
extern "C" void kernel_launch(void* const* d_in, const int* in_sizes, int n_in,
                              void* d_out, int out_size)
{
    const float* Q   = (const float*)d_in[0];
    const float* K   = (const float*)d_in[1];
    const float* V   = (const float*)d_in[2];
    const int*   pad = (const int*)  d_in[3];
    const float* Wq  = (const float*)d_in[4];
    const float* bq  = (const float*)d_in[5];
    const float* Wk  = (const float*)d_in[6];
    const float* bk  = (const float*)d_in[7];
    const float* Wv  = (const float*)d_in[8];
    const float* bv  = (const float*)d_in[9];
    const float* Wo  = (const float*)d_in[10];
    const float* bo  = (const float*)d_in[11];
    float* out = (float*)d_out;

    __nv_bfloat16 *qhi, *khi, *vhi, *vlo, *ahi, *alo, *whi, *wlo;
    cudaGetSymbolAddress((void**)&qhi, g_Qhi);
    cudaGetSymbolAddress((void**)&khi, g_Khi);
    cudaGetSymbolAddress((void**)&vhi, g_Vhi);
    cudaGetSymbolAddress((void**)&vlo, g_Vlo);
    cudaGetSymbolAddress((void**)&ahi, g_Ahi);
    cudaGetSymbolAddress((void**)&alo, g_Alo);
    cudaGetSymbolAddress((void**)&whi, g_Whi);
    cudaGetSymbolAddress((void**)&wlo, g_Wlo);

    cudaFuncSetAttribute(mma_gemm,
                         cudaFuncAttributeMaxDynamicSharedMemorySize, GSMEM);
    cudaFuncSetAttribute(mma_gemm_h1,
                         cudaFuncAttributeMaxDynamicSharedMemorySize, GSMEM1);
    cudaFuncSetAttribute(attn_mma,
                         cudaFuncAttributeMaxDynamicSharedMemorySize, ATTN_SMEM);

    const int n4 = (B_*S_*DM_) / 4;
    const dim3 gw(32, 32), bw(32, 8);
    const dim3 gg(8, 64);

    // Q projection (fp16, single-pass)
    split_wT_h<<<gw, bw>>>(Wq, (__half*)whi);
    cvt_act_h<<<n4/256, 256>>>((const float4*)Q, (uint2*)ahi, n4);
    mma_gemm_h1<<<gg, 128, GSMEM1>>>((const __half*)ahi, (const __half*)whi,
                                     bq, (__half*)qhi);
    // K projection (fp16, single-pass)
    split_wT_h<<<gw, bw>>>(Wk, (__half*)whi);
    cvt_act_h<<<n4/256, 256>>>((const float4*)K, (uint2*)ahi, n4);
    mma_gemm_h1<<<gg, 128, GSMEM1>>>((const __half*)ahi, (const __half*)whi,
                                     bk, (__half*)khi);
    // V projection (bf16x3)
    split_wT<<<gw, bw>>>(Wv, whi, wlo, 0);
    split_act<<<n4/256, 256>>>((const float4*)V, (uint2*)ahi, (uint2*)alo, n4);
    mma_gemm<<<gg, 128, GSMEM>>>(ahi, alo, whi, wlo, bv, nullptr, vhi, vlo, 0);

    // attention -> X hi/lo into ahi/alo
    attn_mma<<<dim3(8, 128), 256, ATTN_SMEM>>>(pad, (const __half*)qhi,
                                               (const __half*)khi, ahi, alo);

    // output projection (bf16x3, fp32 out)
    split_wT<<<gw, bw>>>(Wo, whi, wlo, 1);
    mma_gemm<<<gg, 128, GSMEM>>>(ahi, alo, whi, wlo, bo, out, nullptr, nullptr, 1);
}

// round 11
// speedup vs baseline: 2.6008x; 1.4980x over previous
#include <cuda_runtime.h>
#include <cuda_bf16.h>
#include <cuda_fp16.h>
#include <mma.h>
#include <math.h>
#include <stdint.h>

using namespace nvcuda;

#define S_   1024
#define DM_  1024
#define B_   8
#define H_   16
#define D_   64

// ---------------- scratch (__device__ globals; no allocation) ----------------
__device__ __nv_bfloat16 g_Qhi[B_*H_*S_*D_];  // fp16 payload [b,h,s,d]
__device__ __nv_bfloat16 g_Khi[B_*H_*S_*D_];  // fp16 payload
__device__ __nv_bfloat16 g_Vhi[B_*H_*S_*D_];  // fp16 payload
__device__ __nv_bfloat16 g_Ahi[B_*S_*DM_];    // fp16 act in; then X bf16 hi
__device__ __nv_bfloat16 g_Alo[B_*S_*DM_];    // X bf16 lo
__device__ __nv_bfloat16 g_Whi[DM_*DM_];      // weight-T hi [N][K] (fp16 or bf16)
__device__ __nv_bfloat16 g_Wlo[DM_*DM_];      // weight-T lo (bf16, out proj only)

// ---------------- helpers ----------------
__device__ __forceinline__ uint32_t smem_u32(const void* p) {
    uint32_t a;
    asm("{ .reg .u64 t; cvta.to.shared.u64 t, %1; cvt.u32.u64 %0, t; }"
        : "=r"(a) : "l"(p));
    return a;
}
__device__ __forceinline__ void cp16(uint32_t dst, const void* src) {
    asm volatile("cp.async.cg.shared.global [%0], [%1], 16;" :: "r"(dst), "l"(src));
}
__device__ __forceinline__ uint32_t pack2(float a, float b, float* ra, float* rb) {
    __nv_bfloat16 ha = __float2bfloat16(a), hb = __float2bfloat16(b);
    *ra = a - __bfloat162float(ha);
    *rb = b - __bfloat162float(hb);
    return (uint32_t)__bfloat16_as_ushort(ha) |
           ((uint32_t)__bfloat16_as_ushort(hb) << 16);
}
__device__ __forceinline__ uint32_t pack2lo(float a, float b) {
    __nv_bfloat16 ha = __float2bfloat16(a), hb = __float2bfloat16(b);
    return (uint32_t)__bfloat16_as_ushort(ha) |
           ((uint32_t)__bfloat16_as_ushort(hb) << 16);
}
__device__ __forceinline__ uint32_t pack2h(float a, float b) {
    __half ha = __float2half_rn(a), hb = __float2half_rn(b);
    return (uint32_t)__half_as_ushort(ha) |
           ((uint32_t)__half_as_ushort(hb) << 16);
}

// ---------------- conversion kernels ----------------
// fp16 convert (Q/K/V inputs)
__global__ __launch_bounds__(256) void cvt_act_h(
    const float4* __restrict__ src, uint2* __restrict__ hi, int n4)
{
    int i = blockIdx.x * 256 + threadIdx.x;
    if (i >= n4) return;
    float4 v = src[i];
    uint2 h;
    h.x = pack2h(v.x, v.y);
    h.y = pack2h(v.z, v.w);
    hi[i] = h;
}

// weight transpose+split bf16 (out proj): src=Wo[k][n], out[n][k]
__global__ __launch_bounds__(256) void split_wT(
    const float* __restrict__ W, __nv_bfloat16* __restrict__ hi,
    __nv_bfloat16* __restrict__ lo)
{
    __shared__ float t[32][33];
    int k0 = blockIdx.x * 32, n0 = blockIdx.y * 32;
    int tx = threadIdx.x, ty = threadIdx.y;   // 32 x 8
    #pragma unroll
    for (int i = 0; i < 4; i++) {
        int k = k0 + ty + 8*i, n = n0 + tx;
        t[ty + 8*i][tx] = W[(size_t)k * 1024 + n];
    }
    __syncthreads();
    #pragma unroll
    for (int i = 0; i < 4; i++) {
        int n = n0 + ty + 8*i, k = k0 + tx;
        float v = t[tx][ty + 8*i];
        __nv_bfloat16 h = __float2bfloat16(v);
        __nv_bfloat16 l = __float2bfloat16(v - __bfloat162float(h));
        hi[(size_t)n * 1024 + k] = h;
        lo[(size_t)n * 1024 + k] = l;
    }
}

// weight transpose, fp16 (Q/K/V projections): src=W[h][k][d]
__global__ __launch_bounds__(256) void split_wT_h(
    const float* __restrict__ W, __half* __restrict__ hi)
{
    __shared__ float t[32][33];
    int k0 = blockIdx.x * 32, n0 = blockIdx.y * 32;
    int tx = threadIdx.x, ty = threadIdx.y;
    #pragma unroll
    for (int i = 0; i < 4; i++) {
        int k = k0 + ty + 8*i, n = n0 + tx;
        t[ty + 8*i][tx] = W[(((size_t)(n >> 6)) * 1024 + k) * 64 + (n & 63)];
    }
    __syncthreads();
    #pragma unroll
    for (int i = 0; i < 4; i++) {
        int n = n0 + ty + 8*i, k = k0 + tx;
        hi[(size_t)n * 1024 + k] = __float2half_rn(t[tx][ty + 8*i]);
    }
}

// ---------------- fragment typedefs / sizes ----------------
#define LDSM   40
#define MATB   (128 * LDSM * 2)
#define STAGEB (4 * MATB)
#define GSMEM  (2 * STAGEB + 16 * 128 * 4)
#define STAGEB1 (2 * MATB)
#define EPLD   132
// epilogue smem roundtrip needs 128*EPLD*4 = 67584 B > mainloop (49152 B)
#define GSMEM1 (128 * EPLD * 4)

typedef wmma::fragment<wmma::matrix_a, 16,16,16, __nv_bfloat16, wmma::row_major> FragA;
typedef wmma::fragment<wmma::matrix_b, 16,16,16, __nv_bfloat16, wmma::col_major> FragBc;
typedef wmma::fragment<wmma::matrix_a, 16,16,16, __half, wmma::row_major> HFragA;
typedef wmma::fragment<wmma::matrix_b, 16,16,16, __half, wmma::col_major> HFragB;
typedef wmma::fragment<wmma::matrix_b, 16,16,16, __half, wmma::row_major> HFragBr;
typedef wmma::fragment<wmma::accumulator, 16,16,16, float> FragC;

// ---------------- bf16x3 GEMM (out proj only, fp32 out) ----------------
__device__ __forceinline__ void issue_stage(
    const __nv_bfloat16* __restrict__ Ahi, const __nv_bfloat16* __restrict__ Alo,
    const __nv_bfloat16* __restrict__ Bhi, const __nv_bfloat16* __restrict__ Blo,
    uint32_t sbase, int stage, int m0, int n0, int k0, int tid)
{
    #pragma unroll
    for (int u = 0; u < 16; u++) {
        int chunk = u * 128 + tid;
        int mat = chunk >> 9;
        int r   = (chunk >> 2) & 127;
        int c   = chunk & 3;
        const __nv_bfloat16* g;
        if      (mat == 0) g = Ahi + (size_t)(m0 + r) * 1024 + k0 + c * 8;
        else if (mat == 1) g = Alo + (size_t)(m0 + r) * 1024 + k0 + c * 8;
        else if (mat == 2) g = Bhi + (size_t)(n0 + r) * 1024 + k0 + c * 8;
        else               g = Blo + (size_t)(n0 + r) * 1024 + k0 + c * 8;
        uint32_t dst = sbase + (uint32_t)(stage * STAGEB + mat * MATB + r * (LDSM*2) + c * 16);
        cp16(dst, g);
    }
    asm volatile("cp.async.commit_group;" ::: "memory");
}

__global__ __launch_bounds__(128, 2) void mma_gemm(
    const __nv_bfloat16* __restrict__ Ahi, const __nv_bfloat16* __restrict__ Alo,
    const __nv_bfloat16* __restrict__ Bhi, const __nv_bfloat16* __restrict__ Blo,
    const float* __restrict__ bias, float* __restrict__ outF)
{
    extern __shared__ char sm[];
    float* sBias = (float*)(sm + 2 * STAGEB);
    const uint32_t sbase = smem_u32(sm);
    const int tid = threadIdx.x;
    const int wid = tid >> 5;
    const int m0 = blockIdx.y * 128;
    const int n0 = blockIdx.x * 128;
    const int wm = wid >> 1;
    const int wn = wid & 1;

    for (int idx = tid; idx < 16 * 128; idx += 128)
        sBias[idx] = bias[n0 + (idx & 127)];
    __syncthreads();

    FragC acc[4][4];
    #pragma unroll
    for (int i = 0; i < 4; i++)
        #pragma unroll
        for (int j = 0; j < 4; j++)
            wmma::load_matrix_sync(acc[i][j], sBias + wn*64 + j*16, 128, wmma::mem_row_major);

    issue_stage(Ahi, Alo, Bhi, Blo, sbase, 0, m0, n0, 0, tid);

    for (int kc = 0; kc < 32; kc++) {
        const int s = kc & 1;
        if (kc + 1 < 32) {
            issue_stage(Ahi, Alo, Bhi, Blo, sbase, s ^ 1, m0, n0, (kc + 1) * 32, tid);
            asm volatile("cp.async.wait_group 1;" ::: "memory");
        } else {
            asm volatile("cp.async.wait_group 0;" ::: "memory");
        }
        __syncthreads();

        const __nv_bfloat16* stg = (const __nv_bfloat16*)(sm + s * STAGEB);
        const __nv_bfloat16* sAh = stg;
        const __nv_bfloat16* sAl = stg + 128 * LDSM;
        const __nv_bfloat16* sBh = stg + 2 * 128 * LDSM;
        const __nv_bfloat16* sBl = stg + 3 * 128 * LDSM;

        #pragma unroll
        for (int ks = 0; ks < 2; ks++) {
            FragA ah[4], al[4];
            FragBc bh[4], bl[4];
            #pragma unroll
            for (int i = 0; i < 4; i++) {
                wmma::load_matrix_sync(ah[i], sAh + (wm*64 + i*16) * LDSM + ks*16, LDSM);
                wmma::load_matrix_sync(al[i], sAl + (wm*64 + i*16) * LDSM + ks*16, LDSM);
            }
            #pragma unroll
            for (int j = 0; j < 4; j++) {
                wmma::load_matrix_sync(bh[j], sBh + (wn*64 + j*16) * LDSM + ks*16, LDSM);
                wmma::load_matrix_sync(bl[j], sBl + (wn*64 + j*16) * LDSM + ks*16, LDSM);
            }
            #pragma unroll
            for (int i = 0; i < 4; i++)
                #pragma unroll
                for (int j = 0; j < 4; j++) {
                    wmma::mma_sync(acc[i][j], ah[i], bh[j], acc[i][j]);
                    wmma::mma_sync(acc[i][j], ah[i], bl[j], acc[i][j]);
                    wmma::mma_sync(acc[i][j], al[i], bh[j], acc[i][j]);
                }
        }
        __syncthreads();
    }

    #pragma unroll
    for (int i = 0; i < 4; i++) {
        const int m = m0 + wm*64 + i*16;
        #pragma unroll
        for (int j = 0; j < 4; j++) {
            const int n = n0 + wn*64 + j*16;
            wmma::store_matrix_sync(outF + (size_t)m * 1024 + n, acc[i][j],
                                    1024, wmma::mem_row_major);
        }
    }
}

// ---------------- fp16 single-pass GEMM (Q/K/V projections) -----------------
__device__ __forceinline__ void issue_stage_h1(
    const __half* __restrict__ Ah, const __half* __restrict__ Bh,
    uint32_t sbase, int stage, int m0, int n0, int k0, int tid)
{
    #pragma unroll
    for (int u = 0; u < 8; u++) {
        int chunk = u * 128 + tid;
        int mat = chunk >> 9;
        int r   = (chunk >> 2) & 127;
        int c   = chunk & 3;
        const __half* g = (mat == 0)
            ? Ah + (size_t)(m0 + r) * 1024 + k0 + c * 8
            : Bh + (size_t)(n0 + r) * 1024 + k0 + c * 8;
        uint32_t dst = sbase + (uint32_t)(stage * STAGEB1 + mat * MATB + r * (LDSM*2) + c * 16);
        cp16(dst, g);
    }
    asm volatile("cp.async.commit_group;" ::: "memory");
}

__global__ __launch_bounds__(128, 2) void mma_gemm_h1(
    const __half* __restrict__ Ah, const __half* __restrict__ Bh,
    const float* __restrict__ bias, __half* __restrict__ outH)
{
    extern __shared__ char sm[];
    float* sBias = (float*)(sm + 2 * STAGEB1);
    const uint32_t sbase = smem_u32(sm);
    const int tid = threadIdx.x;
    const int wid = tid >> 5;
    const int m0 = blockIdx.y * 128;
    const int n0 = blockIdx.x * 128;
    const int wm = wid >> 1;
    const int wn = wid & 1;

    for (int idx = tid; idx < 16 * 128; idx += 128)
        sBias[idx] = bias[n0 + (idx & 127)];
    __syncthreads();

    FragC acc[4][4];
    #pragma unroll
    for (int i = 0; i < 4; i++)
        #pragma unroll
        for (int j = 0; j < 4; j++)
            wmma::load_matrix_sync(acc[i][j], sBias + wn*64 + j*16, 128, wmma::mem_row_major);

    issue_stage_h1(Ah, Bh, sbase, 0, m0, n0, 0, tid);

    for (int kc = 0; kc < 32; kc++) {
        const int s = kc & 1;
        if (kc + 1 < 32) {
            issue_stage_h1(Ah, Bh, sbase, s ^ 1, m0, n0, (kc + 1) * 32, tid);
            asm volatile("cp.async.wait_group 1;" ::: "memory");
        } else {
            asm volatile("cp.async.wait_group 0;" ::: "memory");
        }
        __syncthreads();

        const __half* stg = (const __half*)(sm + s * STAGEB1);
        const __half* sAh = stg;
        const __half* sBh = stg + 128 * LDSM;

        #pragma unroll
        for (int ks = 0; ks < 2; ks++) {
            HFragA ah[4];
            HFragB bh[4];
            #pragma unroll
            for (int i = 0; i < 4; i++)
                wmma::load_matrix_sync(ah[i], sAh + (wm*64 + i*16) * LDSM + ks*16, LDSM);
            #pragma unroll
            for (int j = 0; j < 4; j++)
                wmma::load_matrix_sync(bh[j], sBh + (wn*64 + j*16) * LDSM + ks*16, LDSM);
            #pragma unroll
            for (int i = 0; i < 4; i++)
                #pragma unroll
                for (int j = 0; j < 4; j++)
                    wmma::mma_sync(acc[i][j], ah[i], bh[j], acc[i][j]);
        }
        __syncthreads();
    }

    // epilogue: smem roundtrip, fp16 out at [b,h,s,d]
    float* sEpi = (float*)sm;
    #pragma unroll
    for (int i = 0; i < 4; i++)
        #pragma unroll
        for (int j = 0; j < 4; j++)
            wmma::store_matrix_sync(sEpi + (wm*64 + i*16) * EPLD + wn*64 + j*16,
                                    acc[i][j], EPLD, wmma::mem_row_major);
    __syncthreads();

    #pragma unroll
    for (int u = 0; u < 64; u++) {
        int e2 = u * 128 + tid;
        int r = e2 >> 6;
        int c = (e2 & 63) * 2;
        float v0 = sEpi[r * EPLD + c];
        float v1 = sEpi[r * EPLD + c + 1];
        uint32_t hv = pack2h(v0, v1);
        const int m = m0 + r, n = n0 + c;
        const int b = m >> 10, srow = m & 1023;
        const int h = n >> 6,  d = n & 63;
        size_t addr = ((((size_t)(b*16 + h)) * 1024 + srow) * 64 + d);
        *(uint32_t*)(outH + addr) = hv;
    }
}

// ---------------- tensor-core flash attention v5 ----------------------------
// fp16 QK^T single-pass, fp16 PV single-pass. 2 q-tiles/CTA, 2-stage K/V.
// 108.5 KB smem -> 2 CTAs/SM.
#define ALD 72
#define SLD 68
#define TQB 9216
#define oQ   0                          // 2 groups x 1 fp16 tile  18432
#define oKV  18432                      // 2 stages x 2 tiles      36864
#define oP   55296                      // 2 groups x 1 fp16 tile  18432
#define oS   73728                      // 2 groups fp32 64xSLD    34816
#define ATTN_SMEM 108544
#define KVSTG (2 * TQB)

__global__ __launch_bounds__(256, 2) void attn_mma(
    const int* __restrict__ pad,
    const __half* __restrict__ Qg, const __half* __restrict__ Kg,
    const __half* __restrict__ Vg,
    __nv_bfloat16* __restrict__ Xhi, __nv_bfloat16* __restrict__ Xlo)
{
    extern __shared__ char sm[];
    const uint32_t sbase = smem_u32(sm);
    const int tid  = threadIdx.x;
    const int w    = tid >> 5, lane = tid & 31;
    const int g    = w >> 2,   wr   = w & 3;
    const int bx   = blockIdx.x;
    const int bh   = blockIdx.y;
    const int b    = bh >> 4, h = bh & 15;
    const int padb = pad[b];
    const int tlim = S_ - padb;
    const int qt   = bx * 2 + g;
    const int q0   = qt * 64;
    const size_t hoff = (size_t)bh * S_ * D_;

    float* sSg = (float*)(sm + oS + g * 17408);
    __half* sPg = (__half*)(sm + oP + g * TQB);
    const __half* sQ = (const __half*)(sm + oQ + g * TQB);

    // preload: Q tiles (both groups) + K/V tile 0 into stage 0
    #pragma unroll
    for (int u = 0; u < 4; u++) {
        int c = u * 256 + tid;            // 1024 chunks
        int gm = c >> 9;
        int rc = c & 511;
        int r = rc >> 3, cc = rc & 7;
        const __half* src = Qg + hoff + (size_t)((bx*2 + gm) * 64 + r) * 64 + cc * 8;
        cp16(sbase + oQ + (uint32_t)(gm * TQB + r * 144 + cc * 16), src);
    }
    #pragma unroll
    for (int u = 0; u < 4; u++) {
        int c = u * 256 + tid;            // 1024 chunks: K, V
        int mat = c >> 9;
        int rc = c & 511;
        int r = rc >> 3, cc = rc & 7;
        const __half* src = (mat == 0 ? Kg : Vg) + hoff + (size_t)r * 64 + cc * 8;
        cp16(sbase + oKV + (uint32_t)(mat * TQB + r * 144 + cc * 16), src);
    }
    asm volatile("cp.async.commit_group;" ::: "memory");

    const int jtLast = (padb == 0) ? 15 : min(bx * 2 + 1, (tlim - 1) >> 6);

    const int lr = lane >> 1, half = lane & 1;
    const int srow = q0 + wr * 16 + lr;

    float o[32];
    #pragma unroll
    for (int c = 0; c < 32; c++) o[c] = 0.f;
    float mrow = -INFINITY, lrow = 0.f;

    for (int jt = 0; jt <= jtLast; jt++) {
        const int s = jt & 1;
        const int t0 = jt * 64;
        if (jt < jtLast) {
            const int tn = (jt + 1) * 64;
            #pragma unroll
            for (int u = 0; u < 4; u++) {
                int c = u * 256 + tid;
                int mat = c >> 9;
                int rc = c & 511;
                int r = rc >> 3, cc = rc & 7;
                const __half* src = (mat == 0 ? Kg : Vg) + hoff + (size_t)(tn + r) * 64 + cc * 8;
                cp16(sbase + oKV + (uint32_t)((s ^ 1) * KVSTG + mat * TQB + r * 144 + cc * 16), src);
            }
            asm volatile("cp.async.commit_group;" ::: "memory");
            asm volatile("cp.async.wait_group 1;" ::: "memory");
        } else {
            asm volatile("cp.async.wait_group 0;" ::: "memory");
        }
        __syncthreads();

        const bool act = (padb == 0) || (jt <= qt && t0 < tlim);
        if (act) {
            const __half* sK = (const __half*)(sm + oKV + s * KVSTG);
            const __half* sV = (const __half*)(sm + oKV + s * KVSTG + TQB);

            // ---- S = Q K^T (fp16 single-pass) ----
            {
                HFragA qf[4];
                #pragma unroll
                for (int ks = 0; ks < 4; ks++)
                    wmma::load_matrix_sync(qf[ks], sQ + (wr*16) * ALD + ks*16, ALD);
                FragC acc[4];
                #pragma unroll
                for (int j = 0; j < 4; j++) wmma::fill_fragment(acc[j], 0.f);
                #pragma unroll
                for (int j = 0; j < 4; j++) {
                    #pragma unroll
                    for (int ks = 0; ks < 4; ks++) {
                        HFragB kf;
                        wmma::load_matrix_sync(kf, sK + (j*16) * ALD + ks*16, ALD);
                        wmma::mma_sync(acc[j], qf[ks], kf, acc[j]);
                    }
                }
                #pragma unroll
                for (int j = 0; j < 4; j++)
                    wmma::store_matrix_sync(sSg + (wr*16) * SLD + j*16, acc[j],
                                            SLD, wmma::mem_row_major);
            }
            __syncwarp();

            // ---- softmax (regs, vectorized; P -> fp16) ----
            float alpha;
            {
                const float4* Srow4 = (const float4*)(sSg + (wr*16 + lr) * SLD + half * 32);
                const int tbase = t0 + half * 32;
                float v[32];
                #pragma unroll
                for (int q4 = 0; q4 < 8; q4++) {
                    float4 f = Srow4[q4];
                    v[q4*4+0] = f.x; v[q4*4+1] = f.y; v[q4*4+2] = f.z; v[q4*4+3] = f.w;
                }
                float mloc = -INFINITY;
                #pragma unroll
                for (int c = 0; c < 32; c++) {
                    const int t = tbase + c;
                    float val = v[c] * 0.03125f;
                    if ((t > srow) | (t >= tlim) | (padb == 0)) val -= 1e9f;
                    v[c] = val;
                    mloc = fmaxf(mloc, val);
                }
                mloc = fmaxf(mloc, __shfl_xor_sync(0xffffffffu, mloc, 1));
                const float mnew = fmaxf(mrow, mloc);
                alpha = __expf(mrow - mnew);
                uint32_t* Pr32 = (uint32_t*)(sPg + (wr*16 + lr) * ALD + half * 32);
                float lsum = 0.f;
                #pragma unroll
                for (int c = 0; c < 32; c += 2) {
                    float p0 = __expf(v[c]   - mnew);
                    float p1 = __expf(v[c+1] - mnew);
                    lsum += p0; lsum += p1;
                    Pr32[c >> 1] = pack2h(p0, p1);
                }
                lsum += __shfl_xor_sync(0xffffffffu, lsum, 1);
                lrow = lrow * alpha + lsum;
                mrow = mnew;
            }
            __syncwarp();

            // ---- PV (fp16 single-pass), result overwrites S rows ----
            {
                HFragA pf[4];
                #pragma unroll
                for (int ks = 0; ks < 4; ks++)
                    wmma::load_matrix_sync(pf[ks], sPg + (wr*16) * ALD + ks*16, ALD);
                FragC oa[4];
                #pragma unroll
                for (int n = 0; n < 4; n++) wmma::fill_fragment(oa[n], 0.f);
                #pragma unroll
                for (int n = 0; n < 4; n++) {
                    #pragma unroll
                    for (int ks = 0; ks < 4; ks++) {
                        HFragBr vf;
                        wmma::load_matrix_sync(vf, sV + (ks*16) * ALD + n*16, ALD);
                        wmma::mma_sync(oa[n], pf[ks], vf, oa[n]);
                    }
                }
                #pragma unroll
                for (int n = 0; n < 4; n++)
                    wmma::store_matrix_sync(sSg + (wr*16) * SLD + n*16, oa[n],
                                            SLD, wmma::mem_row_major);
            }
            __syncwarp();

            // ---- O = O*alpha + PV (registers) ----
            {
                const float4* Pv4 = (const float4*)(sSg + (wr*16 + lr) * SLD + half * 32);
                #pragma unroll
                for (int q4 = 0; q4 < 8; q4++) {
                    float4 f = Pv4[q4];
                    o[q4*4+0] = o[q4*4+0] * alpha + f.x;
                    o[q4*4+1] = o[q4*4+1] * alpha + f.y;
                    o[q4*4+2] = o[q4*4+2] * alpha + f.z;
                    o[q4*4+3] = o[q4*4+3] * alpha + f.w;
                }
            }
        }
        __syncthreads();
    }

    // epilogue: normalize, split to bf16 hi/lo, store
    {
        const float inv = 1.f / lrow;
        const size_t base = ((size_t)(b * S_ + srow)) * DM_ + h * 64 + half * 32;
        #pragma unroll
        for (int c = 0; c < 32; c += 2) {
            float v0 = o[c] * inv, v1 = o[c+1] * inv;
            float r0, r1;
            uint32_t hv = pack2(v0, v1, &r0, &r1);
            uint32_t lv = pack2lo(r0, r1);
            *(uint32_t*)(Xhi + base + c) = hv;
            *(uint32_t*)(Xlo + base + c) = lv;
        }
    }
}

// ---------------------------------------------------------------------------
extern "C" void kernel_launch(void* const* d_in, const int* in_sizes, int n_in,
                              void* d_out, int out_size)
{
    const float* Q   = (const float*)d_in[0];
    const float* K   = (const float*)d_in[1];
    const float* V   = (const float*)d_in[2];
    const int*   pad = (const int*)  d_in[3];
    const float* Wq  = (const float*)d_in[4];
    const float* bq  = (const float*)d_in[5];
    const float* Wk  = (const float*)d_in[6];
    const float* bk  = (const float*)d_in[7];
    const float* Wv  = (const float*)d_in[8];
    const float* bv  = (const float*)d_in[9];
    const float* Wo  = (const float*)d_in[10];
    const float* bo  = (const float*)d_in[11];
    float* out = (float*)d_out;

    __nv_bfloat16 *qhi, *khi, *vhi, *ahi, *alo, *whi, *wlo;
    cudaGetSymbolAddress((void**)&qhi, g_Qhi);
    cudaGetSymbolAddress((void**)&khi, g_Khi);
    cudaGetSymbolAddress((void**)&vhi, g_Vhi);
    cudaGetSymbolAddress((void**)&ahi, g_Ahi);
    cudaGetSymbolAddress((void**)&alo, g_Alo);
    cudaGetSymbolAddress((void**)&whi, g_Whi);
    cudaGetSymbolAddress((void**)&wlo, g_Wlo);

    cudaFuncSetAttribute(mma_gemm,
                         cudaFuncAttributeMaxDynamicSharedMemorySize, GSMEM);
    cudaFuncSetAttribute(mma_gemm_h1,
                         cudaFuncAttributeMaxDynamicSharedMemorySize, GSMEM1);
    cudaFuncSetAttribute(attn_mma,
                         cudaFuncAttributeMaxDynamicSharedMemorySize, ATTN_SMEM);

    const int n4 = (B_*S_*DM_) / 4;
    const dim3 gw(32, 32), bw(32, 8);
    const dim3 gg(8, 64);

    // Q projection (fp16 single-pass)
    split_wT_h<<<gw, bw>>>(Wq, (__half*)whi);
    cvt_act_h<<<n4/256, 256>>>((const float4*)Q, (uint2*)ahi, n4);
    mma_gemm_h1<<<gg, 128, GSMEM1>>>((const __half*)ahi, (const __half*)whi,
                                     bq, (__half*)qhi);
    // K projection (fp16 single-pass)
    split_wT_h<<<gw, bw>>>(Wk, (__half*)whi);
    cvt_act_h<<<n4/256, 256>>>((const float4*)K, (uint2*)ahi, n4);
    mma_gemm_h1<<<gg, 128, GSMEM1>>>((const __half*)ahi, (const __half*)whi,
                                     bk, (__half*)khi);
    // V projection (fp16 single-pass)
    split_wT_h<<<gw, bw>>>(Wv, (__half*)whi);
    cvt_act_h<<<n4/256, 256>>>((const float4*)V, (uint2*)ahi, n4);
    mma_gemm_h1<<<gg, 128, GSMEM1>>>((const __half*)ahi, (const __half*)whi,
                                     bv, (__half*)vhi);

    // attention (fp16 QK + fp16 PV) -> X bf16 hi/lo into ahi/alo
    attn_mma<<<dim3(8, 128), 256, ATTN_SMEM>>>(pad, (const __half*)qhi,
                                               (const __half*)khi,
                                               (const __half*)vhi, ahi, alo);

    // output projection (bf16x3, fp32 out)
    split_wT<<<gw, bw>>>(Wo, whi, wlo);
    mma_gemm<<<gg, 128, GSMEM>>>(ahi, alo, whi, wlo, bo, out);
}

// round 12
// speedup vs baseline: 2.8488x; 1.0954x over previous
#include <cuda_runtime.h>
#include <cuda_bf16.h>
#include <cuda_fp16.h>
#include <mma.h>
#include <math.h>
#include <stdint.h>

using namespace nvcuda;

#define S_   1024
#define DM_  1024
#define B_   8
#define H_   16
#define D_   64

// ---------------- scratch (__device__ globals; no allocation) ----------------
__device__ __half g_Qh[B_*H_*S_*D_];   // projected Q [b,h,s,d] fp16
__device__ __half g_Kh[B_*H_*S_*D_];   // projected K
__device__ __half g_Vh[B_*H_*S_*D_];   // projected V
__device__ __half g_Ac0[B_*S_*DM_];    // converted Q input; then X fp16 hi
__device__ __half g_Ac1[B_*S_*DM_];    // converted K input; then X fp16 lo (residual)
__device__ __half g_Ac2[B_*S_*DM_];    // converted V input
__device__ __half g_W3[3*DM_*DM_];     // transposed fp16 weights [n][k] x3 (also Wo)

// ---------------- helpers ----------------
__device__ __forceinline__ uint32_t smem_u32(const void* p) {
    uint32_t a;
    asm("{ .reg .u64 t; cvta.to.shared.u64 t, %1; cvt.u32.u64 %0, t; }"
        : "=r"(a) : "l"(p));
    return a;
}
__device__ __forceinline__ void cp16(uint32_t dst, const void* src) {
    asm volatile("cp.async.cg.shared.global [%0], [%1], 16;" :: "r"(dst), "l"(src));
}
__device__ __forceinline__ uint32_t pack2h(float a, float b) {
    __half ha = __float2half_rn(a), hb = __float2half_rn(b);
    return (uint32_t)__half_as_ushort(ha) |
           ((uint32_t)__half_as_ushort(hb) << 16);
}
__device__ __forceinline__ uint32_t pack2hres(float a, float b, float* ra, float* rb) {
    __half ha = __float2half_rn(a), hb = __float2half_rn(b);
    *ra = a - __half2float(ha);
    *rb = b - __half2float(hb);
    return (uint32_t)__half_as_ushort(ha) |
           ((uint32_t)__half_as_ushort(hb) << 16);
}

// ---------------- conversion kernels (batched over z) ----------------
__global__ __launch_bounds__(256) void cvt_act_h3(
    const float4* __restrict__ Q, const float4* __restrict__ K,
    const float4* __restrict__ V, int n4)
{
    int i = blockIdx.x * 256 + threadIdx.x;
    if (i >= n4) return;
    int z = blockIdx.y;
    const float4* src = (z == 0) ? Q : (z == 1) ? K : V;
    uint2* dst = (uint2*)((z == 0) ? g_Ac0 : (z == 1) ? g_Ac1 : g_Ac2);
    float4 v = src[i];
    uint2 h;
    h.x = pack2h(v.x, v.y);
    h.y = pack2h(v.z, v.w);
    dst[i] = h;
}

// weight transpose fp16, batched: src=W[h][k][d] (n=h*64+d) -> g_W3 + z*DM*DM [n][k]
__global__ __launch_bounds__(256) void split_wT_h3(
    const float* __restrict__ Wq, const float* __restrict__ Wk,
    const float* __restrict__ Wv)
{
    __shared__ float t[32][33];
    int k0 = blockIdx.x * 32, n0 = blockIdx.y * 32;
    int z = blockIdx.z;
    const float* W = (z == 0) ? Wq : (z == 1) ? Wk : Wv;
    __half* out = g_W3 + (size_t)z * DM_ * DM_;
    int tx = threadIdx.x, ty = threadIdx.y;
    #pragma unroll
    for (int i = 0; i < 4; i++) {
        int k = k0 + ty + 8*i, n = n0 + tx;
        t[ty + 8*i][tx] = W[(((size_t)(n >> 6)) * 1024 + k) * 64 + (n & 63)];
    }
    __syncthreads();
    #pragma unroll
    for (int i = 0; i < 4; i++) {
        int n = n0 + ty + 8*i, k = k0 + tx;
        out[(size_t)n * 1024 + k] = __float2half_rn(t[tx][ty + 8*i]);
    }
}

// Wo transpose fp16: src=Wo[k][n] -> g_W3 [n][k]
__global__ __launch_bounds__(256) void split_wT_ho(const float* __restrict__ W)
{
    __shared__ float t[32][33];
    int k0 = blockIdx.x * 32, n0 = blockIdx.y * 32;
    int tx = threadIdx.x, ty = threadIdx.y;
    #pragma unroll
    for (int i = 0; i < 4; i++) {
        int k = k0 + ty + 8*i, n = n0 + tx;
        t[ty + 8*i][tx] = W[(size_t)k * 1024 + n];
    }
    __syncthreads();
    #pragma unroll
    for (int i = 0; i < 4; i++) {
        int n = n0 + ty + 8*i, k = k0 + tx;
        g_W3[(size_t)n * 1024 + k] = __float2half_rn(t[tx][ty + 8*i]);
    }
}

// ---------------- fragment typedefs / sizes ----------------
#define LDSM   40
#define MATB   (128 * LDSM * 2)
#define STAGEB1 (2 * MATB)
#define EPLD   132
// mode-0 epilogue smem roundtrip needs 128*EPLD*4 = 67584 B
#define GSMEM1 (128 * EPLD * 4)
#define STAGEB2 (3 * MATB)
#define GSMEM2 (2 * STAGEB2 + 16 * 128 * 4)

typedef wmma::fragment<wmma::matrix_a, 16,16,16, __half, wmma::row_major> HFragA;
typedef wmma::fragment<wmma::matrix_b, 16,16,16, __half, wmma::col_major> HFragB;
typedef wmma::fragment<wmma::matrix_b, 16,16,16, __half, wmma::row_major> HFragBr;
typedef wmma::fragment<wmma::accumulator, 16,16,16, float> FragC;

// ---------------- fp16 single-pass GEMM, batched QKV projections ------------
__device__ __forceinline__ void issue_stage_h1(
    const __half* __restrict__ Ah, const __half* __restrict__ Bh,
    uint32_t sbase, int stage, int m0, int n0, int k0, int tid)
{
    #pragma unroll
    for (int u = 0; u < 8; u++) {
        int chunk = u * 128 + tid;
        int mat = chunk >> 9;
        int r   = (chunk >> 2) & 127;
        int c   = chunk & 3;
        const __half* g = (mat == 0)
            ? Ah + (size_t)(m0 + r) * 1024 + k0 + c * 8
            : Bh + (size_t)(n0 + r) * 1024 + k0 + c * 8;
        uint32_t dst = sbase + (uint32_t)(stage * STAGEB1 + mat * MATB + r * (LDSM*2) + c * 16);
        cp16(dst, g);
    }
    asm volatile("cp.async.commit_group;" ::: "memory");
}

__global__ __launch_bounds__(128, 2) void mma_gemm_h1b(
    const float* __restrict__ bq, const float* __restrict__ bk,
    const float* __restrict__ bv)
{
    extern __shared__ char sm[];
    float* sBias = (float*)(sm + 2 * STAGEB1);
    const uint32_t sbase = smem_u32(sm);
    const int tid = threadIdx.x;
    const int wid = tid >> 5;
    const int m0 = blockIdx.y * 128;
    const int n0 = blockIdx.x * 128;
    const int z  = blockIdx.z;
    const int wm = wid >> 1;
    const int wn = wid & 1;

    const __half* Ah = (z == 0) ? g_Ac0 : (z == 1) ? g_Ac1 : g_Ac2;
    const __half* Bh = g_W3 + (size_t)z * DM_ * DM_;
    const float* bias = (z == 0) ? bq : (z == 1) ? bk : bv;
    __half* outH = (z == 0) ? g_Qh : (z == 1) ? g_Kh : g_Vh;

    for (int idx = tid; idx < 16 * 128; idx += 128)
        sBias[idx] = bias[n0 + (idx & 127)];
    __syncthreads();

    FragC acc[4][4];
    #pragma unroll
    for (int i = 0; i < 4; i++)
        #pragma unroll
        for (int j = 0; j < 4; j++)
            wmma::load_matrix_sync(acc[i][j], sBias + wn*64 + j*16, 128, wmma::mem_row_major);

    issue_stage_h1(Ah, Bh, sbase, 0, m0, n0, 0, tid);

    for (int kc = 0; kc < 32; kc++) {
        const int s = kc & 1;
        if (kc + 1 < 32) {
            issue_stage_h1(Ah, Bh, sbase, s ^ 1, m0, n0, (kc + 1) * 32, tid);
            asm volatile("cp.async.wait_group 1;" ::: "memory");
        } else {
            asm volatile("cp.async.wait_group 0;" ::: "memory");
        }
        __syncthreads();

        const __half* stg = (const __half*)(sm + s * STAGEB1);
        const __half* sAh = stg;
        const __half* sBh = stg + 128 * LDSM;

        #pragma unroll
        for (int ks = 0; ks < 2; ks++) {
            HFragA ah[4];
            HFragB bh[4];
            #pragma unroll
            for (int i = 0; i < 4; i++)
                wmma::load_matrix_sync(ah[i], sAh + (wm*64 + i*16) * LDSM + ks*16, LDSM);
            #pragma unroll
            for (int j = 0; j < 4; j++)
                wmma::load_matrix_sync(bh[j], sBh + (wn*64 + j*16) * LDSM + ks*16, LDSM);
            #pragma unroll
            for (int i = 0; i < 4; i++)
                #pragma unroll
                for (int j = 0; j < 4; j++)
                    wmma::mma_sync(acc[i][j], ah[i], bh[j], acc[i][j]);
        }
        __syncthreads();
    }

    // epilogue: smem roundtrip, fp16 out at [b,h,s,d]
    float* sEpi = (float*)sm;
    #pragma unroll
    for (int i = 0; i < 4; i++)
        #pragma unroll
        for (int j = 0; j < 4; j++)
            wmma::store_matrix_sync(sEpi + (wm*64 + i*16) * EPLD + wn*64 + j*16,
                                    acc[i][j], EPLD, wmma::mem_row_major);
    __syncthreads();

    #pragma unroll
    for (int u = 0; u < 64; u++) {
        int e2 = u * 128 + tid;
        int r = e2 >> 6;
        int c = (e2 & 63) * 2;
        float v0 = sEpi[r * EPLD + c];
        float v1 = sEpi[r * EPLD + c + 1];
        uint32_t hv = pack2h(v0, v1);
        const int m = m0 + r, n = n0 + c;
        const int b = m >> 10, srow = m & 1023;
        const int h = n >> 6,  d = n & 63;
        size_t addr = ((((size_t)(b*16 + h)) * 1024 + srow) * 64 + d);
        *(uint32_t*)(outH + addr) = hv;
    }
}

// ---------------- fp16x2 GEMM (output projection, fp32 out) -----------------
__device__ __forceinline__ void issue_stage_h2(
    const __half* __restrict__ Ah, const __half* __restrict__ Al,
    const __half* __restrict__ Bh,
    uint32_t sbase, int stage, int m0, int n0, int k0, int tid)
{
    #pragma unroll
    for (int u = 0; u < 12; u++) {
        int chunk = u * 128 + tid;         // 1536 chunks of 16B
        int mat = chunk >> 9;
        int r   = (chunk >> 2) & 127;
        int c   = chunk & 3;
        const __half* g;
        if      (mat == 0) g = Ah + (size_t)(m0 + r) * 1024 + k0 + c * 8;
        else if (mat == 1) g = Al + (size_t)(m0 + r) * 1024 + k0 + c * 8;
        else               g = Bh + (size_t)(n0 + r) * 1024 + k0 + c * 8;
        uint32_t dst = sbase + (uint32_t)(stage * STAGEB2 + mat * MATB + r * (LDSM*2) + c * 16);
        cp16(dst, g);
    }
    asm volatile("cp.async.commit_group;" ::: "memory");
}

__global__ __launch_bounds__(128, 2) void mma_gemm_h2f(
    const float* __restrict__ bias, float* __restrict__ outF)
{
    extern __shared__ char sm[];
    float* sBias = (float*)(sm + 2 * STAGEB2);
    const uint32_t sbase = smem_u32(sm);
    const int tid = threadIdx.x;
    const int wid = tid >> 5;
    const int m0 = blockIdx.y * 128;
    const int n0 = blockIdx.x * 128;
    const int wm = wid >> 1;
    const int wn = wid & 1;

    const __half* Ah = g_Ac0;   // X fp16 hi
    const __half* Al = g_Ac1;   // X fp16 residual
    const __half* Bh = g_W3;    // Wo fp16 [n][k]

    for (int idx = tid; idx < 16 * 128; idx += 128)
        sBias[idx] = bias[n0 + (idx & 127)];
    __syncthreads();

    FragC acc[4][4];
    #pragma unroll
    for (int i = 0; i < 4; i++)
        #pragma unroll
        for (int j = 0; j < 4; j++)
            wmma::load_matrix_sync(acc[i][j], sBias + wn*64 + j*16, 128, wmma::mem_row_major);

    issue_stage_h2(Ah, Al, Bh, sbase, 0, m0, n0, 0, tid);

    for (int kc = 0; kc < 32; kc++) {
        const int s = kc & 1;
        if (kc + 1 < 32) {
            issue_stage_h2(Ah, Al, Bh, sbase, s ^ 1, m0, n0, (kc + 1) * 32, tid);
            asm volatile("cp.async.wait_group 1;" ::: "memory");
        } else {
            asm volatile("cp.async.wait_group 0;" ::: "memory");
        }
        __syncthreads();

        const __half* stg = (const __half*)(sm + s * STAGEB2);
        const __half* sAh = stg;
        const __half* sAl = stg + 128 * LDSM;
        const __half* sBh = stg + 2 * 128 * LDSM;

        #pragma unroll
        for (int ks = 0; ks < 2; ks++) {
            HFragA ah[4], al[4];
            HFragB bh[4];
            #pragma unroll
            for (int i = 0; i < 4; i++) {
                wmma::load_matrix_sync(ah[i], sAh + (wm*64 + i*16) * LDSM + ks*16, LDSM);
                wmma::load_matrix_sync(al[i], sAl + (wm*64 + i*16) * LDSM + ks*16, LDSM);
            }
            #pragma unroll
            for (int j = 0; j < 4; j++)
                wmma::load_matrix_sync(bh[j], sBh + (wn*64 + j*16) * LDSM + ks*16, LDSM);
            #pragma unroll
            for (int i = 0; i < 4; i++)
                #pragma unroll
                for (int j = 0; j < 4; j++) {
                    wmma::mma_sync(acc[i][j], ah[i], bh[j], acc[i][j]);
                    wmma::mma_sync(acc[i][j], al[i], bh[j], acc[i][j]);
                }
        }
        __syncthreads();
    }

    #pragma unroll
    for (int i = 0; i < 4; i++) {
        const int m = m0 + wm*64 + i*16;
        #pragma unroll
        for (int j = 0; j < 4; j++) {
            const int n = n0 + wn*64 + j*16;
            wmma::store_matrix_sync(outF + (size_t)m * 1024 + n, acc[i][j],
                                    1024, wmma::mem_row_major);
        }
    }
}

// ---------------- tensor-core flash attention v5 (fp16) ----------------------
#define ALD 72
#define SLD 68
#define TQB 9216
#define oQ   0                          // 2 groups x 1 fp16 tile  18432
#define oKV  18432                      // 2 stages x 2 tiles      36864
#define oP   55296                      // 2 groups x 1 fp16 tile  18432
#define oS   73728                      // 2 groups fp32 64xSLD    34816
#define ATTN_SMEM 108544
#define KVSTG (2 * TQB)

__global__ __launch_bounds__(256, 2) void attn_mma(const int* __restrict__ pad)
{
    extern __shared__ char sm[];
    const uint32_t sbase = smem_u32(sm);
    const int tid  = threadIdx.x;
    const int w    = tid >> 5, lane = tid & 31;
    const int g    = w >> 2,   wr   = w & 3;
    const int bx   = blockIdx.x;
    const int bh   = blockIdx.y;
    const int b    = bh >> 4, h = bh & 15;
    const int padb = pad[b];
    const int tlim = S_ - padb;
    const int qt   = bx * 2 + g;
    const int q0   = qt * 64;
    const size_t hoff = (size_t)bh * S_ * D_;

    float* sSg = (float*)(sm + oS + g * 17408);
    __half* sPg = (__half*)(sm + oP + g * TQB);
    const __half* sQ = (const __half*)(sm + oQ + g * TQB);

    // preload: Q tiles (both groups) + K/V tile 0 into stage 0
    #pragma unroll
    for (int u = 0; u < 4; u++) {
        int c = u * 256 + tid;
        int gm = c >> 9;
        int rc = c & 511;
        int r = rc >> 3, cc = rc & 7;
        const __half* src = g_Qh + hoff + (size_t)((bx*2 + gm) * 64 + r) * 64 + cc * 8;
        cp16(sbase + oQ + (uint32_t)(gm * TQB + r * 144 + cc * 16), src);
    }
    #pragma unroll
    for (int u = 0; u < 4; u++) {
        int c = u * 256 + tid;
        int mat = c >> 9;
        int rc = c & 511;
        int r = rc >> 3, cc = rc & 7;
        const __half* src = (mat == 0 ? g_Kh : g_Vh) + hoff + (size_t)r * 64 + cc * 8;
        cp16(sbase + oKV + (uint32_t)(mat * TQB + r * 144 + cc * 16), src);
    }
    asm volatile("cp.async.commit_group;" ::: "memory");

    const int jtLast = (padb == 0) ? 15 : min(bx * 2 + 1, (tlim - 1) >> 6);

    const int lr = lane >> 1, half = lane & 1;
    const int srow = q0 + wr * 16 + lr;

    float o[32];
    #pragma unroll
    for (int c = 0; c < 32; c++) o[c] = 0.f;
    float mrow = -INFINITY, lrow = 0.f;

    for (int jt = 0; jt <= jtLast; jt++) {
        const int s = jt & 1;
        const int t0 = jt * 64;
        if (jt < jtLast) {
            const int tn = (jt + 1) * 64;
            #pragma unroll
            for (int u = 0; u < 4; u++) {
                int c = u * 256 + tid;
                int mat = c >> 9;
                int rc = c & 511;
                int r = rc >> 3, cc = rc & 7;
                const __half* src = (mat == 0 ? g_Kh : g_Vh) + hoff + (size_t)(tn + r) * 64 + cc * 8;
                cp16(sbase + oKV + (uint32_t)((s ^ 1) * KVSTG + mat * TQB + r * 144 + cc * 16), src);
            }
            asm volatile("cp.async.commit_group;" ::: "memory");
            asm volatile("cp.async.wait_group 1;" ::: "memory");
        } else {
            asm volatile("cp.async.wait_group 0;" ::: "memory");
        }
        __syncthreads();

        const bool act = (padb == 0) || (jt <= qt && t0 < tlim);
        if (act) {
            const __half* sK = (const __half*)(sm + oKV + s * KVSTG);
            const __half* sV = (const __half*)(sm + oKV + s * KVSTG + TQB);

            // ---- S = Q K^T (fp16) ----
            {
                HFragA qf[4];
                #pragma unroll
                for (int ks = 0; ks < 4; ks++)
                    wmma::load_matrix_sync(qf[ks], sQ + (wr*16) * ALD + ks*16, ALD);
                FragC acc[4];
                #pragma unroll
                for (int j = 0; j < 4; j++) wmma::fill_fragment(acc[j], 0.f);
                #pragma unroll
                for (int j = 0; j < 4; j++) {
                    #pragma unroll
                    for (int ks = 0; ks < 4; ks++) {
                        HFragB kf;
                        wmma::load_matrix_sync(kf, sK + (j*16) * ALD + ks*16, ALD);
                        wmma::mma_sync(acc[j], qf[ks], kf, acc[j]);
                    }
                }
                #pragma unroll
                for (int j = 0; j < 4; j++)
                    wmma::store_matrix_sync(sSg + (wr*16) * SLD + j*16, acc[j],
                                            SLD, wmma::mem_row_major);
            }
            __syncwarp();

            // ---- softmax (regs; P -> fp16) ----
            float alpha;
            {
                const float4* Srow4 = (const float4*)(sSg + (wr*16 + lr) * SLD + half * 32);
                const int tbase = t0 + half * 32;
                float v[32];
                #pragma unroll
                for (int q4 = 0; q4 < 8; q4++) {
                    float4 f = Srow4[q4];
                    v[q4*4+0] = f.x; v[q4*4+1] = f.y; v[q4*4+2] = f.z; v[q4*4+3] = f.w;
                }
                float mloc = -INFINITY;
                #pragma unroll
                for (int c = 0; c < 32; c++) {
                    const int t = tbase + c;
                    float val = v[c] * 0.03125f;
                    if ((t > srow) | (t >= tlim) | (padb == 0)) val -= 1e9f;
                    v[c] = val;
                    mloc = fmaxf(mloc, val);
                }
                mloc = fmaxf(mloc, __shfl_xor_sync(0xffffffffu, mloc, 1));
                const float mnew = fmaxf(mrow, mloc);
                alpha = __expf(mrow - mnew);
                uint32_t* Pr32 = (uint32_t*)(sPg + (wr*16 + lr) * ALD + half * 32);
                float lsum = 0.f;
                #pragma unroll
                for (int c = 0; c < 32; c += 2) {
                    float p0 = __expf(v[c]   - mnew);
                    float p1 = __expf(v[c+1] - mnew);
                    lsum += p0; lsum += p1;
                    Pr32[c >> 1] = pack2h(p0, p1);
                }
                lsum += __shfl_xor_sync(0xffffffffu, lsum, 1);
                lrow = lrow * alpha + lsum;
                mrow = mnew;
            }
            __syncwarp();

            // ---- PV (fp16), result overwrites S rows ----
            {
                HFragA pf[4];
                #pragma unroll
                for (int ks = 0; ks < 4; ks++)
                    wmma::load_matrix_sync(pf[ks], sPg + (wr*16) * ALD + ks*16, ALD);
                FragC oa[4];
                #pragma unroll
                for (int n = 0; n < 4; n++) wmma::fill_fragment(oa[n], 0.f);
                #pragma unroll
                for (int n = 0; n < 4; n++) {
                    #pragma unroll
                    for (int ks = 0; ks < 4; ks++) {
                        HFragBr vf;
                        wmma::load_matrix_sync(vf, sV + (ks*16) * ALD + n*16, ALD);
                        wmma::mma_sync(oa[n], pf[ks], vf, oa[n]);
                    }
                }
                #pragma unroll
                for (int n = 0; n < 4; n++)
                    wmma::store_matrix_sync(sSg + (wr*16) * SLD + n*16, oa[n],
                                            SLD, wmma::mem_row_major);
            }
            __syncwarp();

            // ---- O = O*alpha + PV (registers) ----
            {
                const float4* Pv4 = (const float4*)(sSg + (wr*16 + lr) * SLD + half * 32);
                #pragma unroll
                for (int q4 = 0; q4 < 8; q4++) {
                    float4 f = Pv4[q4];
                    o[q4*4+0] = o[q4*4+0] * alpha + f.x;
                    o[q4*4+1] = o[q4*4+1] * alpha + f.y;
                    o[q4*4+2] = o[q4*4+2] * alpha + f.z;
                    o[q4*4+3] = o[q4*4+3] * alpha + f.w;
                }
            }
        }
        __syncthreads();
    }

    // epilogue: normalize, split to fp16 hi + fp16 residual, store to Ac0/Ac1
    {
        const float inv = 1.f / lrow;
        const size_t base = ((size_t)(b * S_ + srow)) * DM_ + h * 64 + half * 32;
        #pragma unroll
        for (int c = 0; c < 32; c += 2) {
            float v0 = o[c] * inv, v1 = o[c+1] * inv;
            float r0, r1;
            uint32_t hv = pack2hres(v0, v1, &r0, &r1);
            uint32_t lv = pack2h(r0, r1);
            *(uint32_t*)(g_Ac0 + base + c) = hv;
            *(uint32_t*)(g_Ac1 + base + c) = lv;
        }
    }
}

// ---------------------------------------------------------------------------
extern "C" void kernel_launch(void* const* d_in, const int* in_sizes, int n_in,
                              void* d_out, int out_size)
{
    const float* Q   = (const float*)d_in[0];
    const float* K   = (const float*)d_in[1];
    const float* V   = (const float*)d_in[2];
    const int*   pad = (const int*)  d_in[3];
    const float* Wq  = (const float*)d_in[4];
    const float* bq  = (const float*)d_in[5];
    const float* Wk  = (const float*)d_in[6];
    const float* bk  = (const float*)d_in[7];
    const float* Wv  = (const float*)d_in[8];
    const float* bv  = (const float*)d_in[9];
    const float* Wo  = (const float*)d_in[10];
    const float* bo  = (const float*)d_in[11];
    float* out = (float*)d_out;

    cudaFuncSetAttribute(mma_gemm_h1b,
                         cudaFuncAttributeMaxDynamicSharedMemorySize, GSMEM1);
    cudaFuncSetAttribute(mma_gemm_h2f,
                         cudaFuncAttributeMaxDynamicSharedMemorySize, GSMEM2);
    cudaFuncSetAttribute(attn_mma,
                         cudaFuncAttributeMaxDynamicSharedMemorySize, ATTN_SMEM);

    const int n4 = (B_*S_*DM_) / 4;

    // convert Q/K/V inputs to fp16 (batched)
    cvt_act_h3<<<dim3(n4/256, 3), 256>>>((const float4*)Q, (const float4*)K,
                                         (const float4*)V, n4);
    // transpose Wq/Wk/Wv to fp16 [n][k] (batched)
    split_wT_h3<<<dim3(32, 32, 3), dim3(32, 8)>>>(Wq, Wk, Wv);
    // Q/K/V projections in one launch
    mma_gemm_h1b<<<dim3(8, 64, 3), 128, GSMEM1>>>(bq, bk, bv);

    // attention -> X fp16 hi/lo into g_Ac0/g_Ac1
    attn_mma<<<dim3(8, 128), 256, ATTN_SMEM>>>(pad);

    // output projection (fp16x2, fp32 out)
    split_wT_ho<<<dim3(32, 32), dim3(32, 8)>>>(Wo);
    mma_gemm_h2f<<<dim3(8, 64), 128, GSMEM2>>>(bo, out);
}